// round 12
// baseline (speedup 1.0000x reference)
#include <cuda_runtime.h>
#include <cuda_bf16.h>
#include <math.h>
#include <stdint.h>

// ---------------- problem constants ----------------
#define LSEQ   2048
#define DMODEL 1024
#define DINNER 2048
#define NH     16
#define DH     128
#define DS     64
#define CONVD  2176          // DINNER + 2*DS
#define DW     4240          // 2*DINNER + 2*DS + NH
#define CHUNK  64
#define NCH    32            // LSEQ / CHUNK

// ---------------- scratch (device globals; allocation is forbidden) ----------------
__device__ __align__(16) float g_xn[LSEQ * DMODEL];
__device__ __align__(16) float g_zx[LSEQ * DW];
__device__ __align__(16) float g_xBC[LSEQ * CONVD];
__device__ __align__(16) float g_dtsp[LSEQ * NH];
__device__ __align__(16) float g_cum[NH * LSEQ];
__device__ __align__(16) float g_cdecay[NH * NCH];
__device__ __align__(16) float g_P[NH * NCH * CHUNK * CHUNK];
__device__ __align__(16) float g_G[NH * NCH * DS * DH];
__device__ __align__(16) float g_S[NH * NCH * DS * DH];
__device__ __align__(16) float g_y[LSEQ * DINNER];
__device__ __align__(16) float g_y2[LSEQ * DINNER];

// ---------------- rmsnorm (input) ----------------
__global__ void __launch_bounds__(256) k_rmsnorm_in(const float* __restrict__ x,
                                                    const float* __restrict__ w) {
    int t = blockIdx.x;
    __shared__ float red[256];
    float s = 0.f;
    for (int j = threadIdx.x; j < DMODEL; j += 256) {
        float v = x[t * DMODEL + j];
        s += v * v;
    }
    red[threadIdx.x] = s; __syncthreads();
    for (int o = 128; o > 0; o >>= 1) {
        if (threadIdx.x < o) red[threadIdx.x] += red[threadIdx.x + o];
        __syncthreads();
    }
    float inv = rsqrtf(red[0] / (float)DMODEL + 1e-5f);
    for (int j = threadIdx.x; j < DMODEL; j += 256)
        g_xn[t * DMODEL + j] = x[t * DMODEL + j] * inv * w[j];
}

// ---------------- tf32 tensor-core GEMM, fragment-pair interleaved smem ----------------
__device__ __forceinline__ uint32_t f2tf32(float x) {
    uint32_t y;
    asm("cvt.rna.tf32.f32 %0, %1;" : "=r"(y) : "f"(x));
    return y;
}
__device__ __forceinline__ void mma_tf32(float c[4], const uint32_t a[4], const uint32_t b[2]) {
    asm("mma.sync.aligned.m16n8k8.row.col.f32.tf32.tf32.f32 "
        "{%0,%1,%2,%3}, {%4,%5,%6,%7}, {%8,%9}, {%0,%1,%2,%3};"
        : "+f"(c[0]), "+f"(c[1]), "+f"(c[2]), "+f"(c[3])
        : "r"(a[0]), "r"(a[1]), "r"(a[2]), "r"(a[3]), "r"(b[0]), "r"(b[1]));
}

// Block tile 128 x (NI*32), BK=8, 256 threads = 8 warps (2M x 4N), warp tile 64 x (NI*8).
// A smem: [8 k-rows][264]: col = (2*(MT*8+g)+half) ^ (kq<<4)  -> (a0,a1)/(a2,a3) are LDS.64 pairs.
// B smem: [4 kpair-rows(tig)][264]: col = 2n + kq            -> (b0,b1) is an LDS.64 pair.
// STS conflict-free (banks 8t+16((w&1)^lq)+i16 / 8t+2j+lq, all 32 distinct);
// LDS.64 conflict-free per 16-lane phase (8*tig + 2g distinct).
template<int NI>
__device__ __forceinline__ void gemm_nt_tf32_body(const float* __restrict__ A,
                                                  const float* __restrict__ B,
                                                  float* __restrict__ C,
                                                  int M, int N, int K) {
    constexpr int BN = NI * 32;
    __shared__ __align__(16) float As[2][8 * 264];   // 8448 B each
    __shared__ __align__(16) float Bs[2][4 * 264];   // 4224 B each

    const int tid  = threadIdx.x;
    const int m0   = blockIdx.y * 128;
    const int n0   = blockIdx.x * BN;
    const int warp = tid >> 5, lane = tid & 31;
    const int wm   = (warp & 1) * 64;
    const int wn   = (warp >> 1) * (NI * 8);
    const int g    = lane >> 2;
    const int tig  = lane & 3;

    const int lrow = tid >> 1;               // 0..127
    const int lq   = tid & 1;                // 16B k-chunk (k = lq*4 + t)
    const bool bload = (NI == 4) || (lrow < 64);

    // interleaved m column for A stores: 2*(MT*8 + (m&7)) + ((m>>3)&1)
    const int innerA = 2 * (((lrow >> 4) << 3) + (lrow & 7)) + ((lrow >> 3) & 1);

    float acc[4][NI][4];
#pragma unroll
    for (int mi = 0; mi < 4; mi++)
#pragma unroll
        for (int ni = 0; ni < NI; ni++)
#pragma unroll
            for (int j = 0; j < 4; j++) acc[mi][ni][j] = 0.f;

    const int KT = K >> 3;
    float4 av, bv;

    auto fetch = [&](int kk) {
        av = *reinterpret_cast<const float4*>(A + (size_t)(m0 + lrow) * K + kk + lq * 4);
        if (bload) {
            int brow = n0 + lrow; if (brow >= N) brow = N - 1;   // clamp; cols masked at store
            bv = *reinterpret_cast<const float4*>(B + (size_t)brow * K + kk + lq * 4);
        }
    };
    auto stage = [&](int buf) {
        float va[4] = {av.x, av.y, av.z, av.w};
#pragma unroll
        for (int t = 0; t < 4; t++)
            As[buf][(lq * 4 + t) * 264 + (innerA ^ (lq << 4))] = __uint_as_float(f2tf32(va[t]));
        if (bload) {
            float vb[4] = {bv.x, bv.y, bv.z, bv.w};
#pragma unroll
            for (int t = 0; t < 4; t++)
                Bs[buf][t * 264 + 2 * lrow + lq] = __uint_as_float(f2tf32(vb[t]));
        }
    };

    fetch(0);
    stage(0);
    __syncthreads();

    for (int kt = 0; kt < KT; kt++) {
        const int buf = kt & 1;
        const bool hasNext = (kt + 1 < KT);
        if (hasNext) fetch((kt + 1) * 8);

        uint32_t af[4][4], bf[NI][2];
#pragma unroll
        for (int mi = 0; mi < 4; mi++) {
            int base = 2 * ((((wm >> 4) + mi) << 3) + g);
            float2 p0 = *reinterpret_cast<const float2*>(&As[buf][tig * 264 + base]);
            float2 p1 = *reinterpret_cast<const float2*>(&As[buf][(tig + 4) * 264 + (base ^ 16)]);
            af[mi][0] = __float_as_uint(p0.x);
            af[mi][1] = __float_as_uint(p0.y);
            af[mi][2] = __float_as_uint(p1.x);
            af[mi][3] = __float_as_uint(p1.y);
        }
#pragma unroll
        for (int ni = 0; ni < NI; ni++) {
            float2 q = *reinterpret_cast<const float2*>(&Bs[buf][tig * 264 + 2 * (wn + ni * 8 + g)]);
            bf[ni][0] = __float_as_uint(q.x);
            bf[ni][1] = __float_as_uint(q.y);
        }
#pragma unroll
        for (int mi = 0; mi < 4; mi++)
#pragma unroll
            for (int ni = 0; ni < NI; ni++)
                mma_tf32(acc[mi][ni], af[mi], bf[ni]);

        if (hasNext) stage(buf ^ 1);
        __syncthreads();
    }

#pragma unroll
    for (int mi = 0; mi < 4; mi++) {
#pragma unroll
        for (int ni = 0; ni < NI; ni++) {
            int r0  = m0 + wm + mi * 16 + g;
            int col = n0 + wn + ni * 8 + 2 * tig;
            if (col < N) {
                *reinterpret_cast<float2*>(&C[(size_t)r0 * N + col]) =
                    make_float2(acc[mi][ni][0], acc[mi][ni][1]);
                *reinterpret_cast<float2*>(&C[(size_t)(r0 + 8) * N + col]) =
                    make_float2(acc[mi][ni][2], acc[mi][ni][3]);
            }
        }
    }
}

__global__ void __launch_bounds__(256, 2) k_gemm1(const float* __restrict__ W) {
    gemm_nt_tf32_body<4>(g_xn, W, g_zx, LSEQ, DW, DMODEL);
}
__global__ void __launch_bounds__(256, 2) k_gemm2(const float* __restrict__ W, float* __restrict__ out) {
    gemm_nt_tf32_body<2>(g_y2, W, out, LSEQ, DMODEL, DINNER);
}

// ---------------- causal conv (width 4) + bias + silu — 4 t-outputs per thread ----------------
__global__ void __launch_bounds__(256) k_conv(const float* __restrict__ conv,
                                              const float* __restrict__ cbias) {
    int c = blockIdx.x * 256 + threadIdx.x;
    if (c >= CONVD) return;
    int t0 = blockIdx.y * 4;

    float cv[4];
#pragma unroll
    for (int m = 0; m < 4; m++) cv[m] = conv[c * 4 + m];
    float bias = cbias[c];

    float zxv[7];
#pragma unroll
    for (int j = 0; j < 7; j++) {
        int ts = t0 - 3 + j;
        zxv[j] = (ts >= 0) ? g_zx[(size_t)ts * DW + DINNER + c] : 0.f;
    }
#pragma unroll
    for (int i = 0; i < 4; i++) {
        float acc = bias;
#pragma unroll
        for (int m = 0; m < 4; m++) acc += zxv[i + 3 - m] * cv[m];
        g_xBC[(size_t)(t0 + i) * CONVD + c] = acc / (1.f + expf(-acc));
    }
}

// ---------------- dt softplus + per-chunk inclusive cumsum of Adt ----------------
__global__ void k_prep(const float* __restrict__ dt_bias, const float* __restrict__ A_log) {
    int ck = blockIdx.x, h = blockIdx.y;
    int tloc = threadIdx.x;
    int gt = ck * CHUNK + tloc;
    __shared__ float s[CHUNK];

    float v = g_zx[(size_t)gt * DW + DINNER + CONVD + h] + dt_bias[h];
    float sp = (v > 20.f) ? v : log1pf(expf(v));
    g_dtsp[gt * NH + h] = sp;
    float a = -expf(A_log[h]) * sp;

    s[tloc] = a; __syncthreads();
#pragma unroll
    for (int off = 1; off < CHUNK; off <<= 1) {
        float add = (tloc >= off) ? s[tloc - off] : 0.f;
        __syncthreads();
        s[tloc] += add;
        __syncthreads();
    }
    g_cum[h * LSEQ + gt] = s[tloc];
    if (tloc == CHUNK - 1) g_cdecay[h * NCH + ck] = expf(s[tloc]);
}

// ---------------- P[t][s] = (t>=s) ? exp(cum[t]-cum[s]) * (C_t . B_s) : 0 ----------------
__global__ void __launch_bounds__(256) k_P() {
    __shared__ float Cs[64 * 64];
    __shared__ float Bsm[64 * 65];
    __shared__ float cum[64];

    int ck = blockIdx.x, h = blockIdx.y;
    int s0 = ck * CHUNK;
    int tid = threadIdx.x;

    for (int e = tid; e < 64 * 64; e += 256) {
        int r = e >> 6, n = e & 63;
        size_t base = (size_t)(s0 + r) * CONVD + DINNER;
        Bsm[r * 65 + n] = g_xBC[base + n];
        Cs [r * 64 + n] = g_xBC[base + DS + n];
    }
    if (tid < 64) cum[tid] = g_cum[h * LSEQ + s0 + tid];
    __syncthreads();

    float* Pout = &g_P[(((size_t)h * NCH + ck) * CHUNK) * CHUNK];
#pragma unroll 1
    for (int i = 0; i < 16; i++) {
        int e = i * 256 + tid;
        int t = e >> 6, s = e & 63;
        float v = 0.f;
        if (t >= s) {
            float dot = 0.f;
#pragma unroll
            for (int n = 0; n < DS; n++) dot += Cs[t * 64 + n] * Bsm[s * 65 + n];
            v = expf(cum[t] - cum[s]) * dot;
        }
        Pout[t * 64 + s] = v;
    }
}

// ---------------- y_intra[t][d] = sum_s P[t][s] * X[s][d] ----------------
__global__ void __launch_bounds__(256) k_yintra() {
    __shared__ float  Ps[64 * 64];
    __shared__ float4 Xs4[64 * 32];

    int ck = blockIdx.x, h = blockIdx.y;
    int s0 = ck * CHUNK;
    int tid = threadIdx.x;

    const float* Pin = &g_P[(((size_t)h * NCH + ck) * CHUNK) * CHUNK];
    for (int e = tid; e < 64 * 64; e += 256) Ps[e] = Pin[e];
    for (int e = tid; e < 64 * 32; e += 256) {
        int s = e >> 5, q = e & 31;
        float4 x = *reinterpret_cast<const float4*>(
            &g_xBC[(size_t)(s0 + s) * CONVD + h * DH + q * 4]);
        float dt = g_dtsp[(s0 + s) * NH + h];
        x.x *= dt; x.y *= dt; x.z *= dt; x.w *= dt;
        Xs4[e] = x;
    }
    __syncthreads();

    int lane = tid & 31, w = tid >> 5;
    float4 acc[8];
#pragma unroll
    for (int i = 0; i < 8; i++) acc[i] = make_float4(0.f, 0.f, 0.f, 0.f);

    for (int s = 0; s < CHUNK; s++) {
        float4 xv = Xs4[s * 32 + lane];
#pragma unroll
        for (int i = 0; i < 8; i++) {
            float p = Ps[(w * 8 + i) * 64 + s];
            acc[i].x += p * xv.x; acc[i].y += p * xv.y;
            acc[i].z += p * xv.z; acc[i].w += p * xv.w;
        }
    }
#pragma unroll
    for (int i = 0; i < 8; i++) {
        int t = w * 8 + i;
        *reinterpret_cast<float4*>(&g_y[(size_t)(s0 + t) * DINNER + h * DH + lane * 4]) = acc[i];
    }
}

// ---------------- G[n][d] = sum_s exp(cumLast - cum[s]) * B[s][n] * X[s][d] ----------------
__global__ void __launch_bounds__(256) k_G() {
    __shared__ float  Bsm[64 * 64];
    __shared__ float4 Xs4[64 * 32];

    int ck = blockIdx.x, h = blockIdx.y;
    int s0 = ck * CHUNK;
    int tid = threadIdx.x;

    float cl = g_cum[h * LSEQ + s0 + 63];
    for (int e = tid; e < 64 * 64; e += 256) {
        int s = e >> 6, n = e & 63;
        Bsm[s * 64 + n] = g_xBC[(size_t)(s0 + s) * CONVD + DINNER + n];
    }
    for (int e = tid; e < 64 * 32; e += 256) {
        int s = e >> 5, q = e & 31;
        float4 x = *reinterpret_cast<const float4*>(
            &g_xBC[(size_t)(s0 + s) * CONVD + h * DH + q * 4]);
        float sc = g_dtsp[(s0 + s) * NH + h] * expf(cl - g_cum[h * LSEQ + s0 + s]);
        x.x *= sc; x.y *= sc; x.z *= sc; x.w *= sc;
        Xs4[e] = x;
    }
    __syncthreads();

    int lane = tid & 31, w = tid >> 5;
    float4 acc[8];
#pragma unroll
    for (int i = 0; i < 8; i++) acc[i] = make_float4(0.f, 0.f, 0.f, 0.f);

    for (int s = 0; s < CHUNK; s++) {
        float4 xv = Xs4[s * 32 + lane];
#pragma unroll
        for (int i = 0; i < 8; i++) {
            float b = Bsm[s * 64 + w * 8 + i];
            acc[i].x += b * xv.x; acc[i].y += b * xv.y;
            acc[i].z += b * xv.z; acc[i].w += b * xv.w;
        }
    }
#pragma unroll
    for (int i = 0; i < 8; i++) {
        int n = w * 8 + i;
        *reinterpret_cast<float4*>(
            &g_G[(((size_t)h * NCH + ck) * DS + n) * DH + lane * 4]) = acc[i];
    }
}

// ---------------- inter-chunk state scan ----------------
__global__ void __launch_bounds__(256) k_scan() {
    int h = blockIdx.x;
    int e4 = blockIdx.y * 256 + threadIdx.x;
    const float4* G4 = reinterpret_cast<const float4*>(&g_G[(size_t)h * NCH * DS * DH]);
    float4* S4 = reinterpret_cast<float4*>(&g_S[(size_t)h * NCH * DS * DH]);
    float4 S = make_float4(0.f, 0.f, 0.f, 0.f);
#pragma unroll
    for (int k = 0; k < NCH; k++) {
        S4[(size_t)k * 2048 + e4] = S;
        float d = g_cdecay[h * NCH + k];
        float4 g = G4[(size_t)k * 2048 + e4];
        S.x = d * S.x + g.x; S.y = d * S.y + g.y;
        S.z = d * S.z + g.z; S.w = d * S.w + g.w;
    }
}

// ---------------- y += exp(cum[t]) * (C_t . S) + D*xh ----------------
__global__ void __launch_bounds__(256) k_inter(const float* __restrict__ Dp) {
    __shared__ float4 Ss4[64 * 32];
    __shared__ float  Csh[64 * 64];

    int ck = blockIdx.x, h = blockIdx.y;
    int s0 = ck * CHUNK;
    int tid = threadIdx.x;

    const float4* Sin = reinterpret_cast<const float4*>(&g_S[((size_t)h * NCH + ck) * DS * DH]);
    for (int e = tid; e < 64 * 32; e += 256) Ss4[e] = Sin[e];
    for (int e = tid; e < 64 * 64; e += 256) {
        int t = e >> 6, n = e & 63;
        Csh[t * 64 + n] = g_xBC[(size_t)(s0 + t) * CONVD + DINNER + DS + n];
    }
    __syncthreads();

    int lane = tid & 31, w = tid >> 5;
    float4 acc[8];
#pragma unroll
    for (int i = 0; i < 8; i++) acc[i] = make_float4(0.f, 0.f, 0.f, 0.f);

    for (int n = 0; n < DS; n++) {
        float4 sv = Ss4[n * 32 + lane];
#pragma unroll
        for (int i = 0; i < 8; i++) {
            float c = Csh[(w * 8 + i) * 64 + n];
            acc[i].x += c * sv.x; acc[i].y += c * sv.y;
            acc[i].z += c * sv.z; acc[i].w += c * sv.w;
        }
    }
    float Dh = Dp[h];
#pragma unroll
    for (int i = 0; i < 8; i++) {
        int t = w * 8 + i, gt = s0 + t;
        float sc = expf(g_cum[h * LSEQ + gt]);
        float4 xh = *reinterpret_cast<const float4*>(
            &g_xBC[(size_t)gt * CONVD + h * DH + lane * 4]);
        float4* yp = reinterpret_cast<float4*>(&g_y[(size_t)gt * DINNER + h * DH + lane * 4]);
        float4 y = *yp;
        y.x += sc * acc[i].x + Dh * xh.x;
        y.y += sc * acc[i].y + Dh * xh.y;
        y.z += sc * acc[i].z + Dh * xh.z;
        y.w += sc * acc[i].w + Dh * xh.w;
        *yp = y;
    }
}

// ---------------- gate (y * silu(z)) + rmsnorm_out ----------------
__global__ void __launch_bounds__(256) k_gatenorm(const float* __restrict__ w) {
    int t = blockIdx.x;
    __shared__ float u[DINNER];
    __shared__ float red[256];
    float s = 0.f;
    for (int j = threadIdx.x; j < DINNER; j += 256) {
        float z = g_zx[(size_t)t * DW + j];
        float yv = g_y[(size_t)t * DINNER + j];
        float uu = yv * (z / (1.f + expf(-z)));
        u[j] = uu;
        s += uu * uu;
    }
    red[threadIdx.x] = s; __syncthreads();
    for (int o = 128; o > 0; o >>= 1) {
        if (threadIdx.x < o) red[threadIdx.x] += red[threadIdx.x + o];
        __syncthreads();
    }
    float inv = rsqrtf(red[0] / (float)DINNER + 1e-5f);
    for (int j = threadIdx.x; j < DINNER; j += 256)
        g_y2[(size_t)t * DINNER + j] = u[j] * inv * w[j];
}

// ---------------- launch sequence: kernel launches ONLY (graph-capture safe) ----------------
extern "C" void kernel_launch(void* const* d_in, const int* in_sizes, int n_in,
                              void* d_out, int out_size) {
    const float* x          = (const float*)d_in[0];
    const float* norm_in_w  = (const float*)d_in[1];
    const float* norm_out_w = (const float*)d_in[2];
    const float* win_w      = (const float*)d_in[3];
    const float* wout_w     = (const float*)d_in[4];
    const float* conv       = (const float*)d_in[5];
    const float* conv_bias  = (const float*)d_in[6];
    const float* dt_bias    = (const float*)d_in[7];
    const float* A_log      = (const float*)d_in[8];
    const float* Dp         = (const float*)d_in[9];
    float* out = (float*)d_out;

    k_rmsnorm_in<<<LSEQ, 256>>>(x, norm_in_w);
    k_gemm1<<<dim3((DW + 127) / 128, LSEQ / 128), 256>>>(win_w);
    k_conv<<<dim3((CONVD + 255) / 256, LSEQ / 4), 256>>>(conv, conv_bias);
    k_prep<<<dim3(NCH, NH), CHUNK>>>(dt_bias, A_log);
    k_P<<<dim3(NCH, NH), 256>>>();
    k_yintra<<<dim3(NCH, NH), 256>>>();
    k_G<<<dim3(NCH, NH), 256>>>();
    k_scan<<<dim3(NH, 8), 256>>>();
    k_inter<<<dim3(NCH, NH), 256>>>(Dp);
    k_gatenorm<<<LSEQ, 256>>>(norm_out_w);
    k_gemm2<<<dim3(DMODEL / 64, LSEQ / 128), 256>>>(wout_w, out);
}

// round 13
// speedup vs baseline: 1.0811x; 1.0811x over previous
#include <cuda_runtime.h>
#include <cuda_bf16.h>
#include <math.h>
#include <stdint.h>

// ---------------- problem constants ----------------
#define LSEQ   2048
#define DMODEL 1024
#define DINNER 2048
#define NH     16
#define DH     128
#define DS     64
#define CONVD  2176          // DINNER + 2*DS
#define DW     4240          // 2*DINNER + 2*DS + NH
#define CHUNK  64
#define NCH    32            // LSEQ / CHUNK

// ---------------- scratch (device globals; allocation is forbidden) ----------------
__device__ __align__(16) float g_xn[LSEQ * DMODEL];
__device__ __align__(16) float g_zx[LSEQ * DW];
__device__ __align__(16) float g_xBC[LSEQ * CONVD];
__device__ __align__(16) float g_dtsp[LSEQ * NH];
__device__ __align__(16) float g_cum[NH * LSEQ];
__device__ __align__(16) float g_cdecay[NH * NCH];
__device__ __align__(16) float g_P[NH * NCH * CHUNK * CHUNK];
__device__ __align__(16) float g_G[NH * NCH * DS * DH];
__device__ __align__(16) float g_S[NH * NCH * DS * DH];
__device__ __align__(16) float g_y[LSEQ * DINNER];
__device__ __align__(16) float g_y2[LSEQ * DINNER];

// ---------------- no-op (launch-index padding so ncu lands on k_gemm1) ----------------
__global__ void k_nop() {}

// ---------------- rmsnorm (input) ----------------
__global__ void __launch_bounds__(256) k_rmsnorm_in(const float* __restrict__ x,
                                                    const float* __restrict__ w) {
    int t = blockIdx.x;
    __shared__ float red[256];
    float s = 0.f;
    for (int j = threadIdx.x; j < DMODEL; j += 256) {
        float v = x[t * DMODEL + j];
        s += v * v;
    }
    red[threadIdx.x] = s; __syncthreads();
    for (int o = 128; o > 0; o >>= 1) {
        if (threadIdx.x < o) red[threadIdx.x] += red[threadIdx.x + o];
        __syncthreads();
    }
    float inv = rsqrtf(red[0] / (float)DMODEL + 1e-5f);
    for (int j = threadIdx.x; j < DMODEL; j += 256)
        g_xn[t * DMODEL + j] = x[t * DMODEL + j] * inv * w[j];
}

// ---------------- tf32 tensor-core GEMM (R11 proven config) ----------------
__device__ __forceinline__ uint32_t f2tf32(float x) {
    uint32_t y;
    asm("cvt.rna.tf32.f32 %0, %1;" : "=r"(y) : "f"(x));
    return y;
}
__device__ __forceinline__ void mma_tf32(float c[4], const uint32_t a[4], const uint32_t b[2]) {
    asm("mma.sync.aligned.m16n8k8.row.col.f32.tf32.tf32.f32 "
        "{%0,%1,%2,%3}, {%4,%5,%6,%7}, {%8,%9}, {%0,%1,%2,%3};"
        : "+f"(c[0]), "+f"(c[1]), "+f"(c[2]), "+f"(c[3])
        : "r"(a[0]), "r"(a[1]), "r"(a[2]), "r"(a[3]), "r"(b[0]), "r"(b[1]));
}

// Block tile 128 x (NI*32), BK=16, 256 threads = 8 warps (2M x 4N), warp tile 64 x (NI*8).
// smem k-major [16][136]; m-index swizzled by XOR((k>>2)<<3) — proven conflict-free.
template<int NI>
__device__ __forceinline__ void gemm_nt_tf32_body(const float* __restrict__ A,
                                                  const float* __restrict__ B,
                                                  float* __restrict__ C,
                                                  int M, int N, int K) {
    constexpr int BN = NI * 32;
    constexpr int BROWS = NI / 2;            // B row-loads per thread (2 or 1)
    __shared__ uint32_t As[2][16][136];
    __shared__ uint32_t Bs[2][16][136];

    const int tid  = threadIdx.x;
    const int m0   = blockIdx.y * 128;
    const int n0   = blockIdx.x * BN;
    const int warp = tid >> 5, lane = tid & 31;
    const int wm   = (warp & 1) * 64;
    const int wn   = (warp >> 1) * (NI * 8);
    const int g    = lane >> 2;
    const int tig  = lane & 3;

    const int lrow = tid >> 2;               // 0..63
    const int lq   = tid & 3;

    float acc[4][NI][4];
#pragma unroll
    for (int mi = 0; mi < 4; mi++)
#pragma unroll
        for (int ni = 0; ni < NI; ni++)
#pragma unroll
            for (int j = 0; j < 4; j++) acc[mi][ni][j] = 0.f;

    const int KT = K >> 4;
    float4 av[2], bv[BROWS];

    auto fetch = [&](int kk) {
#pragma unroll
        for (int r = 0; r < 2; r++) {
            int row = lrow + r * 64;
            av[r] = *reinterpret_cast<const float4*>(A + (size_t)(m0 + row) * K + kk + lq * 4);
        }
#pragma unroll
        for (int r = 0; r < BROWS; r++) {
            int brow = n0 + lrow + r * 64;
            bv[r] = (brow < N)
                  ? *reinterpret_cast<const float4*>(B + (size_t)brow * K + kk + lq * 4)
                  : make_float4(0.f, 0.f, 0.f, 0.f);
        }
    };
    auto stage = [&](int buf) {
#pragma unroll
        for (int r = 0; r < 2; r++) {
            int row = (lrow + r * 64) ^ (lq << 3);
            As[buf][lq * 4 + 0][row] = f2tf32(av[r].x);
            As[buf][lq * 4 + 1][row] = f2tf32(av[r].y);
            As[buf][lq * 4 + 2][row] = f2tf32(av[r].z);
            As[buf][lq * 4 + 3][row] = f2tf32(av[r].w);
        }
#pragma unroll
        for (int r = 0; r < BROWS; r++) {
            int row = (lrow + r * 64) ^ (lq << 3);
            Bs[buf][lq * 4 + 0][row] = f2tf32(bv[r].x);
            Bs[buf][lq * 4 + 1][row] = f2tf32(bv[r].y);
            Bs[buf][lq * 4 + 2][row] = f2tf32(bv[r].z);
            Bs[buf][lq * 4 + 3][row] = f2tf32(bv[r].w);
        }
    };

    fetch(0);
    stage(0);
    __syncthreads();

    for (int kt = 0; kt < KT; kt++) {
        int buf = kt & 1;
        bool hasNext = (kt + 1 < KT);
        if (hasNext) fetch((kt + 1) * 16);

#pragma unroll
        for (int ks = 0; ks < 2; ks++) {
            const int kb = ks * 8;
            const int s0 = (kb >> 2) << 3;
            const int s1 = s0 + 8;
            uint32_t af[4][4], bf[NI][2];
#pragma unroll
            for (int mi = 0; mi < 4; mi++) {
                int mb = wm + mi * 16;
                af[mi][0] = As[buf][kb + tig][(mb ^ s0) + g];
                af[mi][1] = As[buf][kb + tig][((mb + 8) ^ s0) + g];
                af[mi][2] = As[buf][kb + tig + 4][(mb ^ s1) + g];
                af[mi][3] = As[buf][kb + tig + 4][((mb + 8) ^ s1) + g];
            }
#pragma unroll
            for (int ni = 0; ni < NI; ni++) {
                int nb = wn + ni * 8;
                bf[ni][0] = Bs[buf][kb + tig][(nb ^ s0) + g];
                bf[ni][1] = Bs[buf][kb + tig + 4][(nb ^ s1) + g];
            }
#pragma unroll
            for (int mi = 0; mi < 4; mi++)
#pragma unroll
                for (int ni = 0; ni < NI; ni++)
                    mma_tf32(acc[mi][ni], af[mi], bf[ni]);
        }

        if (hasNext) stage(buf ^ 1);
        __syncthreads();
    }

#pragma unroll
    for (int mi = 0; mi < 4; mi++) {
#pragma unroll
        for (int ni = 0; ni < NI; ni++) {
            int r0  = m0 + wm + mi * 16 + g;
            int col = n0 + wn + ni * 8 + 2 * tig;
            if (col < N) {
                *reinterpret_cast<float2*>(&C[(size_t)r0 * N + col]) =
                    make_float2(acc[mi][ni][0], acc[mi][ni][1]);
                *reinterpret_cast<float2*>(&C[(size_t)(r0 + 8) * N + col]) =
                    make_float2(acc[mi][ni][2], acc[mi][ni][3]);
            }
        }
    }
}

__global__ void __launch_bounds__(256) k_gemm1(const float* __restrict__ W) {
    gemm_nt_tf32_body<4>(g_xn, W, g_zx, LSEQ, DW, DMODEL);
}
__global__ void __launch_bounds__(256) k_gemm2(const float* __restrict__ W, float* __restrict__ out) {
    gemm_nt_tf32_body<2>(g_y2, W, out, LSEQ, DMODEL, DINNER);
}

// ---------------- causal conv (width 4) + bias + silu — 4 t-outputs per thread ----------------
__global__ void __launch_bounds__(256) k_conv(const float* __restrict__ conv,
                                              const float* __restrict__ cbias) {
    int c = blockIdx.x * 256 + threadIdx.x;
    if (c >= CONVD) return;
    int t0 = blockIdx.y * 4;

    float cv[4];
#pragma unroll
    for (int m = 0; m < 4; m++) cv[m] = conv[c * 4 + m];
    float bias = cbias[c];

    float zxv[7];
#pragma unroll
    for (int j = 0; j < 7; j++) {
        int ts = t0 - 3 + j;
        zxv[j] = (ts >= 0) ? g_zx[(size_t)ts * DW + DINNER + c] : 0.f;
    }
#pragma unroll
    for (int i = 0; i < 4; i++) {
        float acc = bias;
#pragma unroll
        for (int m = 0; m < 4; m++) acc += zxv[i + 3 - m] * cv[m];
        g_xBC[(size_t)(t0 + i) * CONVD + c] = acc / (1.f + expf(-acc));
    }
}

// ---------------- dt softplus + per-chunk inclusive cumsum of Adt ----------------
__global__ void k_prep(const float* __restrict__ dt_bias, const float* __restrict__ A_log) {
    int ck = blockIdx.x, h = blockIdx.y;
    int tloc = threadIdx.x;
    int gt = ck * CHUNK + tloc;
    __shared__ float s[CHUNK];

    float v = g_zx[(size_t)gt * DW + DINNER + CONVD + h] + dt_bias[h];
    float sp = (v > 20.f) ? v : log1pf(expf(v));
    g_dtsp[gt * NH + h] = sp;
    float a = -expf(A_log[h]) * sp;

    s[tloc] = a; __syncthreads();
#pragma unroll
    for (int off = 1; off < CHUNK; off <<= 1) {
        float add = (tloc >= off) ? s[tloc - off] : 0.f;
        __syncthreads();
        s[tloc] += add;
        __syncthreads();
    }
    g_cum[h * LSEQ + gt] = s[tloc];
    if (tloc == CHUNK - 1) g_cdecay[h * NCH + ck] = expf(s[tloc]);
}

// ---------------- P[t][s] = (t>=s) ? exp(cum[t]-cum[s]) * (C_t . B_s) : 0 ----------------
__global__ void __launch_bounds__(256) k_P() {
    __shared__ float Cs[64 * 64];
    __shared__ float Bsm[64 * 65];
    __shared__ float cum[64];

    int ck = blockIdx.x, h = blockIdx.y;
    int s0 = ck * CHUNK;
    int tid = threadIdx.x;

    for (int e = tid; e < 64 * 64; e += 256) {
        int r = e >> 6, n = e & 63;
        size_t base = (size_t)(s0 + r) * CONVD + DINNER;
        Bsm[r * 65 + n] = g_xBC[base + n];
        Cs [r * 64 + n] = g_xBC[base + DS + n];
    }
    if (tid < 64) cum[tid] = g_cum[h * LSEQ + s0 + tid];
    __syncthreads();

    float* Pout = &g_P[(((size_t)h * NCH + ck) * CHUNK) * CHUNK];
#pragma unroll 1
    for (int i = 0; i < 16; i++) {
        int e = i * 256 + tid;
        int t = e >> 6, s = e & 63;
        float v = 0.f;
        if (t >= s) {
            float dot = 0.f;
#pragma unroll
            for (int n = 0; n < DS; n++) dot += Cs[t * 64 + n] * Bsm[s * 65 + n];
            v = expf(cum[t] - cum[s]) * dot;
        }
        Pout[t * 64 + s] = v;
    }
}

// ---------------- y_intra[t][d] = sum_s P[t][s] * X[s][d] ----------------
__global__ void __launch_bounds__(256) k_yintra() {
    __shared__ float  Ps[64 * 64];
    __shared__ float4 Xs4[64 * 32];

    int ck = blockIdx.x, h = blockIdx.y;
    int s0 = ck * CHUNK;
    int tid = threadIdx.x;

    const float* Pin = &g_P[(((size_t)h * NCH + ck) * CHUNK) * CHUNK];
    for (int e = tid; e < 64 * 64; e += 256) Ps[e] = Pin[e];
    for (int e = tid; e < 64 * 32; e += 256) {
        int s = e >> 5, q = e & 31;
        float4 x = *reinterpret_cast<const float4*>(
            &g_xBC[(size_t)(s0 + s) * CONVD + h * DH + q * 4]);
        float dt = g_dtsp[(s0 + s) * NH + h];
        x.x *= dt; x.y *= dt; x.z *= dt; x.w *= dt;
        Xs4[e] = x;
    }
    __syncthreads();

    int lane = tid & 31, w = tid >> 5;
    float4 acc[8];
#pragma unroll
    for (int i = 0; i < 8; i++) acc[i] = make_float4(0.f, 0.f, 0.f, 0.f);

    for (int s = 0; s < CHUNK; s++) {
        float4 xv = Xs4[s * 32 + lane];
#pragma unroll
        for (int i = 0; i < 8; i++) {
            float p = Ps[(w * 8 + i) * 64 + s];
            acc[i].x += p * xv.x; acc[i].y += p * xv.y;
            acc[i].z += p * xv.z; acc[i].w += p * xv.w;
        }
    }
#pragma unroll
    for (int i = 0; i < 8; i++) {
        int t = w * 8 + i;
        *reinterpret_cast<float4*>(&g_y[(size_t)(s0 + t) * DINNER + h * DH + lane * 4]) = acc[i];
    }
}

// ---------------- G[n][d] = sum_s exp(cumLast - cum[s]) * B[s][n] * X[s][d] ----------------
__global__ void __launch_bounds__(256) k_G() {
    __shared__ float  Bsm[64 * 64];
    __shared__ float4 Xs4[64 * 32];

    int ck = blockIdx.x, h = blockIdx.y;
    int s0 = ck * CHUNK;
    int tid = threadIdx.x;

    float cl = g_cum[h * LSEQ + s0 + 63];
    for (int e = tid; e < 64 * 64; e += 256) {
        int s = e >> 6, n = e & 63;
        Bsm[s * 64 + n] = g_xBC[(size_t)(s0 + s) * CONVD + DINNER + n];
    }
    for (int e = tid; e < 64 * 32; e += 256) {
        int s = e >> 5, q = e & 31;
        float4 x = *reinterpret_cast<const float4*>(
            &g_xBC[(size_t)(s0 + s) * CONVD + h * DH + q * 4]);
        float sc = g_dtsp[(s0 + s) * NH + h] * expf(cl - g_cum[h * LSEQ + s0 + s]);
        x.x *= sc; x.y *= sc; x.z *= sc; x.w *= sc;
        Xs4[e] = x;
    }
    __syncthreads();

    int lane = tid & 31, w = tid >> 5;
    float4 acc[8];
#pragma unroll
    for (int i = 0; i < 8; i++) acc[i] = make_float4(0.f, 0.f, 0.f, 0.f);

    for (int s = 0; s < CHUNK; s++) {
        float4 xv = Xs4[s * 32 + lane];
#pragma unroll
        for (int i = 0; i < 8; i++) {
            float b = Bsm[s * 64 + w * 8 + i];
            acc[i].x += b * xv.x; acc[i].y += b * xv.y;
            acc[i].z += b * xv.z; acc[i].w += b * xv.w;
        }
    }
#pragma unroll
    for (int i = 0; i < 8; i++) {
        int n = w * 8 + i;
        *reinterpret_cast<float4*>(
            &g_G[(((size_t)h * NCH + ck) * DS + n) * DH + lane * 4]) = acc[i];
    }
}

// ---------------- inter-chunk state scan ----------------
__global__ void __launch_bounds__(256) k_scan() {
    int h = blockIdx.x;
    int e4 = blockIdx.y * 256 + threadIdx.x;
    const float4* G4 = reinterpret_cast<const float4*>(&g_G[(size_t)h * NCH * DS * DH]);
    float4* S4 = reinterpret_cast<float4*>(&g_S[(size_t)h * NCH * DS * DH]);
    float4 S = make_float4(0.f, 0.f, 0.f, 0.f);
#pragma unroll
    for (int k = 0; k < NCH; k++) {
        S4[(size_t)k * 2048 + e4] = S;
        float d = g_cdecay[h * NCH + k];
        float4 g = G4[(size_t)k * 2048 + e4];
        S.x = d * S.x + g.x; S.y = d * S.y + g.y;
        S.z = d * S.z + g.z; S.w = d * S.w + g.w;
    }
}

// ---------------- y += exp(cum[t]) * (C_t . S) + D*xh ----------------
__global__ void __launch_bounds__(256) k_inter(const float* __restrict__ Dp) {
    __shared__ float4 Ss4[64 * 32];
    __shared__ float  Csh[64 * 64];

    int ck = blockIdx.x, h = blockIdx.y;
    int s0 = ck * CHUNK;
    int tid = threadIdx.x;

    const float4* Sin = reinterpret_cast<const float4*>(&g_S[((size_t)h * NCH + ck) * DS * DH]);
    for (int e = tid; e < 64 * 32; e += 256) Ss4[e] = Sin[e];
    for (int e = tid; e < 64 * 64; e += 256) {
        int t = e >> 6, n = e & 63;
        Csh[t * 64 + n] = g_xBC[(size_t)(s0 + t) * CONVD + DINNER + DS + n];
    }
    __syncthreads();

    int lane = tid & 31, w = tid >> 5;
    float4 acc[8];
#pragma unroll
    for (int i = 0; i < 8; i++) acc[i] = make_float4(0.f, 0.f, 0.f, 0.f);

    for (int n = 0; n < DS; n++) {
        float4 sv = Ss4[n * 32 + lane];
#pragma unroll
        for (int i = 0; i < 8; i++) {
            float c = Csh[(w * 8 + i) * 64 + n];
            acc[i].x += c * sv.x; acc[i].y += c * sv.y;
            acc[i].z += c * sv.z; acc[i].w += c * sv.w;
        }
    }
    float Dh = Dp[h];
#pragma unroll
    for (int i = 0; i < 8; i++) {
        int t = w * 8 + i, gt = s0 + t;
        float sc = expf(g_cum[h * LSEQ + gt]);
        float4 xh = *reinterpret_cast<const float4*>(
            &g_xBC[(size_t)gt * CONVD + h * DH + lane * 4]);
        float4* yp = reinterpret_cast<float4*>(&g_y[(size_t)gt * DINNER + h * DH + lane * 4]);
        float4 y = *yp;
        y.x += sc * acc[i].x + Dh * xh.x;
        y.y += sc * acc[i].y + Dh * xh.y;
        y.z += sc * acc[i].z + Dh * xh.z;
        y.w += sc * acc[i].w + Dh * xh.w;
        *yp = y;
    }
}

// ---------------- gate (y * silu(z)) + rmsnorm_out ----------------
__global__ void __launch_bounds__(256) k_gatenorm(const float* __restrict__ w) {
    int t = blockIdx.x;
    __shared__ float u[DINNER];
    __shared__ float red[256];
    float s = 0.f;
    for (int j = threadIdx.x; j < DINNER; j += 256) {
        float z = g_zx[(size_t)t * DW + j];
        float yv = g_y[(size_t)t * DINNER + j];
        float uu = yv * (z / (1.f + expf(-z)));
        u[j] = uu;
        s += uu * uu;
    }
    red[threadIdx.x] = s; __syncthreads();
    for (int o = 128; o > 0; o >>= 1) {
        if (threadIdx.x < o) red[threadIdx.x] += red[threadIdx.x + o];
        __syncthreads();
    }
    float inv = rsqrtf(red[0] / (float)DINNER + 1e-5f);
    for (int j = threadIdx.x; j < DINNER; j += 256)
        g_y2[(size_t)t * DINNER + j] = u[j] * inv * w[j];
}

// ---------------- launch sequence: kernel launches ONLY (graph-capture safe) ----------------
extern "C" void kernel_launch(void* const* d_in, const int* in_sizes, int n_in,
                              void* d_out, int out_size) {
    const float* x          = (const float*)d_in[0];
    const float* norm_in_w  = (const float*)d_in[1];
    const float* norm_out_w = (const float*)d_in[2];
    const float* win_w      = (const float*)d_in[3];
    const float* wout_w     = (const float*)d_in[4];
    const float* conv       = (const float*)d_in[5];
    const float* conv_bias  = (const float*)d_in[6];
    const float* dt_bias    = (const float*)d_in[7];
    const float* A_log      = (const float*)d_in[8];
    const float* Dp         = (const float*)d_in[9];
    float* out = (float*)d_out;

    k_rmsnorm_in<<<LSEQ, 256>>>(x, norm_in_w);          // launch 0
    k_nop<<<1, 32>>>();                                  // launch 1 (index padding)
    k_nop<<<1, 32>>>();                                  // launch 2 (index padding)
    k_gemm1<<<dim3((DW + 127) / 128, LSEQ / 128), 256>>>(win_w);   // launch 3 -> ncu target
    k_conv<<<dim3((CONVD + 255) / 256, LSEQ / 4), 256>>>(conv, conv_bias);
    k_prep<<<dim3(NCH, NH), CHUNK>>>(dt_bias, A_log);
    k_P<<<dim3(NCH, NH), 256>>>();
    k_yintra<<<dim3(NCH, NH), 256>>>();
    k_G<<<dim3(NCH, NH), 256>>>();
    k_scan<<<dim3(NH, 8), 256>>>();
    k_inter<<<dim3(NCH, NH), 256>>>(Dp);
    k_gatenorm<<<LSEQ, 256>>>(norm_out_w);
    k_gemm2<<<dim3(DMODEL / 64, LSEQ / 128), 256>>>(wout_w, out);
}

// round 14
// speedup vs baseline: 1.1091x; 1.0259x over previous
#include <cuda_runtime.h>
#include <cuda_bf16.h>
#include <math.h>
#include <stdint.h>

// ---------------- problem constants ----------------
#define LSEQ   2048
#define DMODEL 1024
#define DINNER 2048
#define NH     16
#define DH     128
#define DS     64
#define CONVD  2176          // DINNER + 2*DS
#define DW     4240          // 2*DINNER + 2*DS + NH
#define CHUNK  64
#define NCH    32            // LSEQ / CHUNK

// ---------------- scratch (device globals; allocation is forbidden) ----------------
__device__ __align__(16) float g_xn[LSEQ * DMODEL];
__device__ __align__(16) float g_zx[LSEQ * DW];
__device__ __align__(16) float g_xBC[LSEQ * CONVD];
__device__ __align__(16) float g_dtsp[LSEQ * NH];
__device__ __align__(16) float g_cum[NH * LSEQ];
__device__ __align__(16) float g_cdecay[NH * NCH];
__device__ __align__(16) float g_P[NH * NCH * CHUNK * CHUNK];
__device__ __align__(16) float g_G[NH * NCH * DS * DH];
__device__ __align__(16) float g_S[NH * NCH * DS * DH];
__device__ __align__(16) float g_y[LSEQ * DINNER];
__device__ __align__(16) float g_y2[LSEQ * DINNER];

// ---------------- no-op (launch-index padding so ncu lands on k_gemm1) ----------------
__global__ void k_nop() {}

// ---------------- rmsnorm (input) ----------------
__global__ void __launch_bounds__(256) k_rmsnorm_in(const float* __restrict__ x,
                                                    const float* __restrict__ w) {
    int t = blockIdx.x;
    __shared__ float red[256];
    float s = 0.f;
    for (int j = threadIdx.x; j < DMODEL; j += 256) {
        float v = x[t * DMODEL + j];
        s += v * v;
    }
    red[threadIdx.x] = s; __syncthreads();
    for (int o = 128; o > 0; o >>= 1) {
        if (threadIdx.x < o) red[threadIdx.x] += red[threadIdx.x + o];
        __syncthreads();
    }
    float inv = rsqrtf(red[0] / (float)DMODEL + 1e-5f);
    for (int j = threadIdx.x; j < DMODEL; j += 256)
        g_xn[t * DMODEL + j] = x[t * DMODEL + j] * inv * w[j];
}

// ---------------- tf32 tensor-core GEMM (R11 config + 2 CTAs/SM) ----------------
__device__ __forceinline__ uint32_t f2tf32(float x) {
    uint32_t y;
    asm("cvt.rna.tf32.f32 %0, %1;" : "=r"(y) : "f"(x));
    return y;
}
__device__ __forceinline__ void mma_tf32(float c[4], const uint32_t a[4], const uint32_t b[2]) {
    asm("mma.sync.aligned.m16n8k8.row.col.f32.tf32.tf32.f32 "
        "{%0,%1,%2,%3}, {%4,%5,%6,%7}, {%8,%9}, {%0,%1,%2,%3};"
        : "+f"(c[0]), "+f"(c[1]), "+f"(c[2]), "+f"(c[3])
        : "r"(a[0]), "r"(a[1]), "r"(a[2]), "r"(a[3]), "r"(b[0]), "r"(b[1]));
}

// Block tile 128 x (NI*32), BK=16, 256 threads = 8 warps (2M x 4N), warp tile 64 x (NI*8).
// smem k-major [16][136]; m-index swizzled by XOR((k>>2)<<3) — proven conflict-free.
template<int NI>
__device__ __forceinline__ void gemm_nt_tf32_body(const float* __restrict__ A,
                                                  const float* __restrict__ B,
                                                  float* __restrict__ C,
                                                  int M, int N, int K) {
    constexpr int BN = NI * 32;
    constexpr int BROWS = NI / 2;            // B row-loads per thread (2 or 1)
    __shared__ uint32_t As[2][16][136];
    __shared__ uint32_t Bs[2][16][136];

    const int tid  = threadIdx.x;
    const int m0   = blockIdx.y * 128;
    const int n0   = blockIdx.x * BN;
    const int warp = tid >> 5, lane = tid & 31;
    const int wm   = (warp & 1) * 64;
    const int wn   = (warp >> 1) * (NI * 8);
    const int g    = lane >> 2;
    const int tig  = lane & 3;

    const int lrow = tid >> 2;               // 0..63
    const int lq   = tid & 3;

    float acc[4][NI][4];
#pragma unroll
    for (int mi = 0; mi < 4; mi++)
#pragma unroll
        for (int ni = 0; ni < NI; ni++)
#pragma unroll
            for (int j = 0; j < 4; j++) acc[mi][ni][j] = 0.f;

    const int KT = K >> 4;
    float4 av[2], bv[BROWS];

    auto fetch = [&](int kk) {
#pragma unroll
        for (int r = 0; r < 2; r++) {
            int row = lrow + r * 64;
            av[r] = *reinterpret_cast<const float4*>(A + (size_t)(m0 + row) * K + kk + lq * 4);
        }
#pragma unroll
        for (int r = 0; r < BROWS; r++) {
            int brow = n0 + lrow + r * 64;
            bv[r] = (brow < N)
                  ? *reinterpret_cast<const float4*>(B + (size_t)brow * K + kk + lq * 4)
                  : make_float4(0.f, 0.f, 0.f, 0.f);
        }
    };
    auto stage = [&](int buf) {
#pragma unroll
        for (int r = 0; r < 2; r++) {
            int row = (lrow + r * 64) ^ (lq << 3);
            As[buf][lq * 4 + 0][row] = f2tf32(av[r].x);
            As[buf][lq * 4 + 1][row] = f2tf32(av[r].y);
            As[buf][lq * 4 + 2][row] = f2tf32(av[r].z);
            As[buf][lq * 4 + 3][row] = f2tf32(av[r].w);
        }
#pragma unroll
        for (int r = 0; r < BROWS; r++) {
            int row = (lrow + r * 64) ^ (lq << 3);
            Bs[buf][lq * 4 + 0][row] = f2tf32(bv[r].x);
            Bs[buf][lq * 4 + 1][row] = f2tf32(bv[r].y);
            Bs[buf][lq * 4 + 2][row] = f2tf32(bv[r].z);
            Bs[buf][lq * 4 + 3][row] = f2tf32(bv[r].w);
        }
    };

    fetch(0);
    stage(0);
    __syncthreads();

    for (int kt = 0; kt < KT; kt++) {
        int buf = kt & 1;
        bool hasNext = (kt + 1 < KT);
        if (hasNext) fetch((kt + 1) * 16);

#pragma unroll
        for (int ks = 0; ks < 2; ks++) {
            const int kb = ks * 8;
            const int s0 = (kb >> 2) << 3;
            const int s1 = s0 + 8;
            uint32_t af[4][4], bf[NI][2];
#pragma unroll
            for (int mi = 0; mi < 4; mi++) {
                int mb = wm + mi * 16;
                af[mi][0] = As[buf][kb + tig][(mb ^ s0) + g];
                af[mi][1] = As[buf][kb + tig][((mb + 8) ^ s0) + g];
                af[mi][2] = As[buf][kb + tig + 4][(mb ^ s1) + g];
                af[mi][3] = As[buf][kb + tig + 4][((mb + 8) ^ s1) + g];
            }
#pragma unroll
            for (int ni = 0; ni < NI; ni++) {
                int nb = wn + ni * 8;
                bf[ni][0] = Bs[buf][kb + tig][(nb ^ s0) + g];
                bf[ni][1] = Bs[buf][kb + tig + 4][(nb ^ s1) + g];
            }
#pragma unroll
            for (int mi = 0; mi < 4; mi++)
#pragma unroll
                for (int ni = 0; ni < NI; ni++)
                    mma_tf32(acc[mi][ni], af[mi], bf[ni]);
        }

        if (hasNext) stage(buf ^ 1);
        __syncthreads();
    }

#pragma unroll
    for (int mi = 0; mi < 4; mi++) {
#pragma unroll
        for (int ni = 0; ni < NI; ni++) {
            int r0  = m0 + wm + mi * 16 + g;
            int col = n0 + wn + ni * 8 + 2 * tig;
            if (col < N) {
                *reinterpret_cast<float2*>(&C[(size_t)r0 * N + col]) =
                    make_float2(acc[mi][ni][0], acc[mi][ni][1]);
                *reinterpret_cast<float2*>(&C[(size_t)(r0 + 8) * N + col]) =
                    make_float2(acc[mi][ni][2], acc[mi][ni][3]);
            }
        }
    }
}

__global__ void __launch_bounds__(256, 2) k_gemm1(const float* __restrict__ W) {
    gemm_nt_tf32_body<4>(g_xn, W, g_zx, LSEQ, DW, DMODEL);
}
__global__ void __launch_bounds__(256, 2) k_gemm2(const float* __restrict__ W, float* __restrict__ out) {
    gemm_nt_tf32_body<2>(g_y2, W, out, LSEQ, DMODEL, DINNER);
}

// ---------------- causal conv (width 4) + bias + silu — 4 t-outputs per thread ----------------
__global__ void __launch_bounds__(256) k_conv(const float* __restrict__ conv,
                                              const float* __restrict__ cbias) {
    int c = blockIdx.x * 256 + threadIdx.x;
    if (c >= CONVD) return;
    int t0 = blockIdx.y * 4;

    float cv[4];
#pragma unroll
    for (int m = 0; m < 4; m++) cv[m] = conv[c * 4 + m];
    float bias = cbias[c];

    float zxv[7];
#pragma unroll
    for (int j = 0; j < 7; j++) {
        int ts = t0 - 3 + j;
        zxv[j] = (ts >= 0) ? g_zx[(size_t)ts * DW + DINNER + c] : 0.f;
    }
#pragma unroll
    for (int i = 0; i < 4; i++) {
        float acc = bias;
#pragma unroll
        for (int m = 0; m < 4; m++) acc += zxv[i + 3 - m] * cv[m];
        g_xBC[(size_t)(t0 + i) * CONVD + c] = acc / (1.f + expf(-acc));
    }
}

// ---------------- dt softplus + per-chunk inclusive cumsum of Adt ----------------
__global__ void k_prep(const float* __restrict__ dt_bias, const float* __restrict__ A_log) {
    int ck = blockIdx.x, h = blockIdx.y;
    int tloc = threadIdx.x;
    int gt = ck * CHUNK + tloc;
    __shared__ float s[CHUNK];

    float v = g_zx[(size_t)gt * DW + DINNER + CONVD + h] + dt_bias[h];
    float sp = (v > 20.f) ? v : log1pf(expf(v));
    g_dtsp[gt * NH + h] = sp;
    float a = -expf(A_log[h]) * sp;

    s[tloc] = a; __syncthreads();
#pragma unroll
    for (int off = 1; off < CHUNK; off <<= 1) {
        float add = (tloc >= off) ? s[tloc - off] : 0.f;
        __syncthreads();
        s[tloc] += add;
        __syncthreads();
    }
    g_cum[h * LSEQ + gt] = s[tloc];
    if (tloc == CHUNK - 1) g_cdecay[h * NCH + ck] = expf(s[tloc]);
}

// ---------------- P[t][s] = (t>=s) ? exp(cum[t]-cum[s]) * (C_t . B_s) : 0 ----------------
__global__ void __launch_bounds__(256) k_P() {
    __shared__ float Cs[64 * 64];
    __shared__ float Bsm[64 * 65];
    __shared__ float cum[64];

    int ck = blockIdx.x, h = blockIdx.y;
    int s0 = ck * CHUNK;
    int tid = threadIdx.x;

    for (int e = tid; e < 64 * 64; e += 256) {
        int r = e >> 6, n = e & 63;
        size_t base = (size_t)(s0 + r) * CONVD + DINNER;
        Bsm[r * 65 + n] = g_xBC[base + n];
        Cs [r * 64 + n] = g_xBC[base + DS + n];
    }
    if (tid < 64) cum[tid] = g_cum[h * LSEQ + s0 + tid];
    __syncthreads();

    float* Pout = &g_P[(((size_t)h * NCH + ck) * CHUNK) * CHUNK];
#pragma unroll 1
    for (int i = 0; i < 16; i++) {
        int e = i * 256 + tid;
        int t = e >> 6, s = e & 63;
        float v = 0.f;
        if (t >= s) {
            float dot = 0.f;
#pragma unroll
            for (int n = 0; n < DS; n++) dot += Cs[t * 64 + n] * Bsm[s * 65 + n];
            v = expf(cum[t] - cum[s]) * dot;
        }
        Pout[t * 64 + s] = v;
    }
}

// ---------------- y_intra[t][d] = sum_s P[t][s] * X[s][d] ----------------
__global__ void __launch_bounds__(256) k_yintra() {
    __shared__ float  Ps[64 * 64];
    __shared__ float4 Xs4[64 * 32];

    int ck = blockIdx.x, h = blockIdx.y;
    int s0 = ck * CHUNK;
    int tid = threadIdx.x;

    const float* Pin = &g_P[(((size_t)h * NCH + ck) * CHUNK) * CHUNK];
    for (int e = tid; e < 64 * 64; e += 256) Ps[e] = Pin[e];
    for (int e = tid; e < 64 * 32; e += 256) {
        int s = e >> 5, q = e & 31;
        float4 x = *reinterpret_cast<const float4*>(
            &g_xBC[(size_t)(s0 + s) * CONVD + h * DH + q * 4]);
        float dt = g_dtsp[(s0 + s) * NH + h];
        x.x *= dt; x.y *= dt; x.z *= dt; x.w *= dt;
        Xs4[e] = x;
    }
    __syncthreads();

    int lane = tid & 31, w = tid >> 5;
    float4 acc[8];
#pragma unroll
    for (int i = 0; i < 8; i++) acc[i] = make_float4(0.f, 0.f, 0.f, 0.f);

    for (int s = 0; s < CHUNK; s++) {
        float4 xv = Xs4[s * 32 + lane];
#pragma unroll
        for (int i = 0; i < 8; i++) {
            float p = Ps[(w * 8 + i) * 64 + s];
            acc[i].x += p * xv.x; acc[i].y += p * xv.y;
            acc[i].z += p * xv.z; acc[i].w += p * xv.w;
        }
    }
#pragma unroll
    for (int i = 0; i < 8; i++) {
        int t = w * 8 + i;
        *reinterpret_cast<float4*>(&g_y[(size_t)(s0 + t) * DINNER + h * DH + lane * 4]) = acc[i];
    }
}

// ---------------- G[n][d] = sum_s exp(cumLast - cum[s]) * B[s][n] * X[s][d] ----------------
__global__ void __launch_bounds__(256) k_G() {
    __shared__ float  Bsm[64 * 64];
    __shared__ float4 Xs4[64 * 32];

    int ck = blockIdx.x, h = blockIdx.y;
    int s0 = ck * CHUNK;
    int tid = threadIdx.x;

    float cl = g_cum[h * LSEQ + s0 + 63];
    for (int e = tid; e < 64 * 64; e += 256) {
        int s = e >> 6, n = e & 63;
        Bsm[s * 64 + n] = g_xBC[(size_t)(s0 + s) * CONVD + DINNER + n];
    }
    for (int e = tid; e < 64 * 32; e += 256) {
        int s = e >> 5, q = e & 31;
        float4 x = *reinterpret_cast<const float4*>(
            &g_xBC[(size_t)(s0 + s) * CONVD + h * DH + q * 4]);
        float sc = g_dtsp[(s0 + s) * NH + h] * expf(cl - g_cum[h * LSEQ + s0 + s]);
        x.x *= sc; x.y *= sc; x.z *= sc; x.w *= sc;
        Xs4[e] = x;
    }
    __syncthreads();

    int lane = tid & 31, w = tid >> 5;
    float4 acc[8];
#pragma unroll
    for (int i = 0; i < 8; i++) acc[i] = make_float4(0.f, 0.f, 0.f, 0.f);

    for (int s = 0; s < CHUNK; s++) {
        float4 xv = Xs4[s * 32 + lane];
#pragma unroll
        for (int i = 0; i < 8; i++) {
            float b = Bsm[s * 64 + w * 8 + i];
            acc[i].x += b * xv.x; acc[i].y += b * xv.y;
            acc[i].z += b * xv.z; acc[i].w += b * xv.w;
        }
    }
#pragma unroll
    for (int i = 0; i < 8; i++) {
        int n = w * 8 + i;
        *reinterpret_cast<float4*>(
            &g_G[(((size_t)h * NCH + ck) * DS + n) * DH + lane * 4]) = acc[i];
    }
}

// ---------------- inter-chunk state scan ----------------
__global__ void __launch_bounds__(256) k_scan() {
    int h = blockIdx.x;
    int e4 = blockIdx.y * 256 + threadIdx.x;
    const float4* G4 = reinterpret_cast<const float4*>(&g_G[(size_t)h * NCH * DS * DH]);
    float4* S4 = reinterpret_cast<float4*>(&g_S[(size_t)h * NCH * DS * DH]);
    float4 S = make_float4(0.f, 0.f, 0.f, 0.f);
#pragma unroll
    for (int k = 0; k < NCH; k++) {
        S4[(size_t)k * 2048 + e4] = S;
        float d = g_cdecay[h * NCH + k];
        float4 g = G4[(size_t)k * 2048 + e4];
        S.x = d * S.x + g.x; S.y = d * S.y + g.y;
        S.z = d * S.z + g.z; S.w = d * S.w + g.w;
    }
}

// ---------------- y += exp(cum[t]) * (C_t . S) + D*xh ----------------
__global__ void __launch_bounds__(256) k_inter(const float* __restrict__ Dp) {
    __shared__ float4 Ss4[64 * 32];
    __shared__ float  Csh[64 * 64];

    int ck = blockIdx.x, h = blockIdx.y;
    int s0 = ck * CHUNK;
    int tid = threadIdx.x;

    const float4* Sin = reinterpret_cast<const float4*>(&g_S[((size_t)h * NCH + ck) * DS * DH]);
    for (int e = tid; e < 64 * 32; e += 256) Ss4[e] = Sin[e];
    for (int e = tid; e < 64 * 64; e += 256) {
        int t = e >> 6, n = e & 63;
        Csh[t * 64 + n] = g_xBC[(size_t)(s0 + t) * CONVD + DINNER + DS + n];
    }
    __syncthreads();

    int lane = tid & 31, w = tid >> 5;
    float4 acc[8];
#pragma unroll
    for (int i = 0; i < 8; i++) acc[i] = make_float4(0.f, 0.f, 0.f, 0.f);

    for (int n = 0; n < DS; n++) {
        float4 sv = Ss4[n * 32 + lane];
#pragma unroll
        for (int i = 0; i < 8; i++) {
            float c = Csh[(w * 8 + i) * 64 + n];
            acc[i].x += c * sv.x; acc[i].y += c * sv.y;
            acc[i].z += c * sv.z; acc[i].w += c * sv.w;
        }
    }
    float Dh = Dp[h];
#pragma unroll
    for (int i = 0; i < 8; i++) {
        int t = w * 8 + i, gt = s0 + t;
        float sc = expf(g_cum[h * LSEQ + gt]);
        float4 xh = *reinterpret_cast<const float4*>(
            &g_xBC[(size_t)gt * CONVD + h * DH + lane * 4]);
        float4* yp = reinterpret_cast<float4*>(&g_y[(size_t)gt * DINNER + h * DH + lane * 4]);
        float4 y = *yp;
        y.x += sc * acc[i].x + Dh * xh.x;
        y.y += sc * acc[i].y + Dh * xh.y;
        y.z += sc * acc[i].z + Dh * xh.z;
        y.w += sc * acc[i].w + Dh * xh.w;
        *yp = y;
    }
}

// ---------------- gate (y * silu(z)) + rmsnorm_out ----------------
__global__ void __launch_bounds__(256) k_gatenorm(const float* __restrict__ w) {
    int t = blockIdx.x;
    __shared__ float u[DINNER];
    __shared__ float red[256];
    float s = 0.f;
    for (int j = threadIdx.x; j < DINNER; j += 256) {
        float z = g_zx[(size_t)t * DW + j];
        float yv = g_y[(size_t)t * DINNER + j];
        float uu = yv * (z / (1.f + expf(-z)));
        u[j] = uu;
        s += uu * uu;
    }
    red[threadIdx.x] = s; __syncthreads();
    for (int o = 128; o > 0; o >>= 1) {
        if (threadIdx.x < o) red[threadIdx.x] += red[threadIdx.x + o];
        __syncthreads();
    }
    float inv = rsqrtf(red[0] / (float)DINNER + 1e-5f);
    for (int j = threadIdx.x; j < DINNER; j += 256)
        g_y2[(size_t)t * DINNER + j] = u[j] * inv * w[j];
}

// ---------------- launch sequence: kernel launches ONLY (graph-capture safe) ----------------
extern "C" void kernel_launch(void* const* d_in, const int* in_sizes, int n_in,
                              void* d_out, int out_size) {
    const float* x          = (const float*)d_in[0];
    const float* norm_in_w  = (const float*)d_in[1];
    const float* norm_out_w = (const float*)d_in[2];
    const float* win_w      = (const float*)d_in[3];
    const float* wout_w     = (const float*)d_in[4];
    const float* conv       = (const float*)d_in[5];
    const float* conv_bias  = (const float*)d_in[6];
    const float* dt_bias    = (const float*)d_in[7];
    const float* A_log      = (const float*)d_in[8];
    const float* Dp         = (const float*)d_in[9];
    float* out = (float*)d_out;

    k_rmsnorm_in<<<LSEQ, 256>>>(x, norm_in_w);          // launch 0
    k_nop<<<1, 32>>>();                                  // launch 1 (index padding)
    k_nop<<<1, 32>>>();                                  // launch 2 (index padding)
    k_gemm1<<<dim3((DW + 127) / 128, LSEQ / 128), 256>>>(win_w);   // launch 3 -> ncu target
    k_conv<<<dim3((CONVD + 255) / 256, LSEQ / 4), 256>>>(conv, conv_bias);
    k_prep<<<dim3(NCH, NH), CHUNK>>>(dt_bias, A_log);
    k_P<<<dim3(NCH, NH), 256>>>();
    k_yintra<<<dim3(NCH, NH), 256>>>();
    k_G<<<dim3(NCH, NH), 256>>>();
    k_scan<<<dim3(NH, 8), 256>>>();
    k_inter<<<dim3(NCH, NH), 256>>>(Dp);
    k_gatenorm<<<LSEQ, 256>>>(norm_out_w);
    k_gemm2<<<dim3(DMODEL / 64, LSEQ / 128), 256>>>(wout_w, out);
}

// round 16
// speedup vs baseline: 1.1528x; 1.0394x over previous
#include <cuda_runtime.h>
#include <cuda_bf16.h>
#include <math.h>
#include <stdint.h>

// ---------------- problem constants ----------------
#define LSEQ   2048
#define DMODEL 1024
#define DINNER 2048
#define NH     16
#define DH     128
#define DS     64
#define CONVD  2176          // DINNER + 2*DS
#define DW     4240          // 2*DINNER + 2*DS + NH
#define CHUNK  64
#define NCH    32            // LSEQ / CHUNK

// ---------------- scratch (device globals; allocation is forbidden) ----------------
__device__ __align__(16) float g_xn[LSEQ * DMODEL];
__device__ __align__(16) float g_zx[LSEQ * DW];
__device__ __align__(16) float g_xBC[LSEQ * CONVD];
__device__ __align__(16) float g_dtsp[LSEQ * NH];
__device__ __align__(16) float g_cum[NH * LSEQ];
__device__ __align__(16) float g_cdecay[NH * NCH];
__device__ __align__(16) float g_P[NH * NCH * CHUNK * CHUNK];
__device__ __align__(16) float g_G[NH * NCH * DS * DH];
__device__ __align__(16) float g_S[NH * NCH * DS * DH];
__device__ __align__(16) float g_y[LSEQ * DINNER];
__device__ __align__(16) float g_y2[LSEQ * DINNER];

// ---------------- no-op (launch-index padding so ncu lands on k_gemm1) ----------------
__global__ void k_nop() {}

// ---------------- rmsnorm (input) ----------------
__global__ void __launch_bounds__(256) k_rmsnorm_in(const float* __restrict__ x,
                                                    const float* __restrict__ w) {
    int t = blockIdx.x;
    __shared__ float red[256];
    float s = 0.f;
    for (int j = threadIdx.x; j < DMODEL; j += 256) {
        float v = x[t * DMODEL + j];
        s += v * v;
    }
    red[threadIdx.x] = s; __syncthreads();
    for (int o = 128; o > 0; o >>= 1) {
        if (threadIdx.x < o) red[threadIdx.x] += red[threadIdx.x + o];
        __syncthreads();
    }
    float inv = rsqrtf(red[0] / (float)DMODEL + 1e-5f);
    for (int j = threadIdx.x; j < DMODEL; j += 256)
        g_xn[t * DMODEL + j] = x[t * DMODEL + j] * inv * w[j];
}

// ---------------- tf32 helpers ----------------
__device__ __forceinline__ uint32_t f2tf32(float x) {
    uint32_t y;
    asm("cvt.rna.tf32.f32 %0, %1;" : "=r"(y) : "f"(x));
    return y;
}
__device__ __forceinline__ void mma_tf32(float c[4], const uint32_t a[4], const uint32_t b[2]) {
    asm("mma.sync.aligned.m16n8k8.row.col.f32.tf32.tf32.f32 "
        "{%0,%1,%2,%3}, {%4,%5,%6,%7}, {%8,%9}, {%0,%1,%2,%3};"
        : "+f"(c[0]), "+f"(c[1]), "+f"(c[2]), "+f"(c[3])
        : "r"(a[0]), "r"(a[1]), "r"(a[2]), "r"(a[3]), "r"(b[0]), "r"(b[1]));
}

// ---------------- GEMM1: CTA 256x128, warps 4M x 2N, warp tile 64x64 ----------------
// Unpadded strides (256/128) + fine XOR swizzle: element (m,k) stored at column
// m ^ ((((k&3) ^ ((k>>2)&3)) << 3)). STS banks: lrow ^ ((j^lq)<<3) -> 32 distinct.
// Fragment LDS banks: g (bits0-2) ^ tig (bits3-4) -> 32 distinct. smem = 48KB exactly.
__global__ void __launch_bounds__(256, 1) k_gemm1(const float* __restrict__ W) {
    const float* A = g_xn;
    const float* B = W;
    float* C = g_zx;
    const int N = DW, K = DMODEL;

    __shared__ uint32_t As[2][16][256];
    __shared__ uint32_t Bs[2][16][128];

    const int tid  = threadIdx.x;
    const int m0   = blockIdx.y * 256;
    const int n0   = blockIdx.x * 128;
    const int warp = tid >> 5, lane = tid & 31;
    const int wm   = (warp & 3) * 64;     // 4 warps in M
    const int wn   = (warp >> 2) * 64;    // 2 warps in N
    const int g    = lane >> 2;
    const int tig  = lane & 3;

    const int lrow = tid >> 2;            // 0..63
    const int lq   = tid & 3;

    float acc[4][8][4];
#pragma unroll
    for (int mi = 0; mi < 4; mi++)
#pragma unroll
        for (int ni = 0; ni < 8; ni++)
#pragma unroll
            for (int j = 0; j < 4; j++) acc[mi][ni][j] = 0.f;

    const int KT = K >> 4;
    float4 av[4], bv[2];

    auto fetch = [&](int kk) {
#pragma unroll
        for (int r = 0; r < 4; r++) {
            int row = lrow + r * 64;
            av[r] = *reinterpret_cast<const float4*>(A + (size_t)(m0 + row) * K + kk + lq * 4);
        }
#pragma unroll
        for (int r = 0; r < 2; r++) {
            int brow = n0 + lrow + r * 64;
            bv[r] = (brow < N)
                  ? *reinterpret_cast<const float4*>(B + (size_t)brow * K + kk + lq * 4)
                  : make_float4(0.f, 0.f, 0.f, 0.f);
        }
    };
    auto stage = [&](int buf) {
#pragma unroll
        for (int r = 0; r < 4; r++) {
            int row = lrow + r * 64;
            float va[4] = {av[r].x, av[r].y, av[r].z, av[r].w};
#pragma unroll
            for (int j = 0; j < 4; j++)
                As[buf][lq * 4 + j][row ^ ((j ^ lq) << 3)] = f2tf32(va[j]);
        }
#pragma unroll
        for (int r = 0; r < 2; r++) {
            int row = lrow + r * 64;
            float vb[4] = {bv[r].x, bv[r].y, bv[r].z, bv[r].w};
#pragma unroll
            for (int j = 0; j < 4; j++)
                Bs[buf][lq * 4 + j][row ^ ((j ^ lq) << 3)] = f2tf32(vb[j]);
        }
    };

    fetch(0);
    stage(0);
    __syncthreads();

    for (int kt = 0; kt < KT; kt++) {
        int buf = kt & 1;
        bool hasNext = (kt + 1 < KT);
        if (hasNext) fetch((kt + 1) * 16);

#pragma unroll
        for (int ks = 0; ks < 2; ks++) {
            const int kb = ks * 8;
            const int sw0 = (tig ^ (kb >> 2)) << 3;         // k in [kb, kb+4)
            const int sw1 = (tig ^ ((kb >> 2) + 1)) << 3;   // k in [kb+4, kb+8)
            uint32_t af[4][4], bf[8][2];
#pragma unroll
            for (int mi = 0; mi < 4; mi++) {
                int mb = wm + mi * 16;
                af[mi][0] = As[buf][kb + tig][(mb ^ sw0) + g];
                af[mi][1] = As[buf][kb + tig][((mb + 8) ^ sw0) + g];
                af[mi][2] = As[buf][kb + tig + 4][(mb ^ sw1) + g];
                af[mi][3] = As[buf][kb + tig + 4][((mb + 8) ^ sw1) + g];
            }
#pragma unroll
            for (int ni = 0; ni < 8; ni++) {
                int nb = wn + ni * 8;
                bf[ni][0] = Bs[buf][kb + tig][(nb ^ sw0) + g];
                bf[ni][1] = Bs[buf][kb + tig + 4][(nb ^ sw1) + g];
            }
#pragma unroll
            for (int mi = 0; mi < 4; mi++)
#pragma unroll
                for (int ni = 0; ni < 8; ni++)
                    mma_tf32(acc[mi][ni], af[mi], bf[ni]);
        }

        if (hasNext) stage(buf ^ 1);
        __syncthreads();
    }

#pragma unroll
    for (int mi = 0; mi < 4; mi++) {
#pragma unroll
        for (int ni = 0; ni < 8; ni++) {
            int r0  = m0 + wm + mi * 16 + g;
            int col = n0 + wn + ni * 8 + 2 * tig;
            if (col < N) {
                *reinterpret_cast<float2*>(&C[(size_t)r0 * N + col]) =
                    make_float2(acc[mi][ni][0], acc[mi][ni][1]);
                *reinterpret_cast<float2*>(&C[(size_t)(r0 + 8) * N + col]) =
                    make_float2(acc[mi][ni][2], acc[mi][ni][3]);
            }
        }
    }
}

// ---------------- GEMM2: proven 128x64 config (R11/R14) ----------------
__global__ void __launch_bounds__(256, 2) k_gemm2(const float* __restrict__ W, float* __restrict__ out) {
    const float* A = g_y2;
    const float* B = W;
    float* C = out;
    const int N = DMODEL, K = DINNER;
    constexpr int NI = 2;
    constexpr int BN = NI * 32;

    __shared__ uint32_t As[2][16][136];
    __shared__ uint32_t Bs[2][16][136];

    const int tid  = threadIdx.x;
    const int m0   = blockIdx.y * 128;
    const int n0   = blockIdx.x * BN;
    const int warp = tid >> 5, lane = tid & 31;
    const int wm   = (warp & 1) * 64;
    const int wn   = (warp >> 1) * (NI * 8);
    const int g    = lane >> 2;
    const int tig  = lane & 3;

    const int lrow = tid >> 2;
    const int lq   = tid & 3;

    float acc[4][NI][4];
#pragma unroll
    for (int mi = 0; mi < 4; mi++)
#pragma unroll
        for (int ni = 0; ni < NI; ni++)
#pragma unroll
            for (int j = 0; j < 4; j++) acc[mi][ni][j] = 0.f;

    const int KT = K >> 4;
    float4 av[2], bv[1];

    auto fetch = [&](int kk) {
#pragma unroll
        for (int r = 0; r < 2; r++) {
            int row = lrow + r * 64;
            av[r] = *reinterpret_cast<const float4*>(A + (size_t)(m0 + row) * K + kk + lq * 4);
        }
        {
            int brow = n0 + lrow;
            bv[0] = (brow < N)
                  ? *reinterpret_cast<const float4*>(B + (size_t)brow * K + kk + lq * 4)
                  : make_float4(0.f, 0.f, 0.f, 0.f);
        }
    };
    auto stage = [&](int buf) {
#pragma unroll
        for (int r = 0; r < 2; r++) {
            int row = (lrow + r * 64) ^ (lq << 3);
            As[buf][lq * 4 + 0][row] = f2tf32(av[r].x);
            As[buf][lq * 4 + 1][row] = f2tf32(av[r].y);
            As[buf][lq * 4 + 2][row] = f2tf32(av[r].z);
            As[buf][lq * 4 + 3][row] = f2tf32(av[r].w);
        }
        {
            int row = lrow ^ (lq << 3);
            Bs[buf][lq * 4 + 0][row] = f2tf32(bv[0].x);
            Bs[buf][lq * 4 + 1][row] = f2tf32(bv[0].y);
            Bs[buf][lq * 4 + 2][row] = f2tf32(bv[0].z);
            Bs[buf][lq * 4 + 3][row] = f2tf32(bv[0].w);
        }
    };

    fetch(0);
    stage(0);
    __syncthreads();

    for (int kt = 0; kt < KT; kt++) {
        int buf = kt & 1;
        bool hasNext = (kt + 1 < KT);
        if (hasNext) fetch((kt + 1) * 16);

#pragma unroll
        for (int ks = 0; ks < 2; ks++) {
            const int kb = ks * 8;
            const int s0 = (kb >> 2) << 3;
            const int s1 = s0 + 8;
            uint32_t af[4][4], bf[NI][2];
#pragma unroll
            for (int mi = 0; mi < 4; mi++) {
                int mb = wm + mi * 16;
                af[mi][0] = As[buf][kb + tig][(mb ^ s0) + g];
                af[mi][1] = As[buf][kb + tig][((mb + 8) ^ s0) + g];
                af[mi][2] = As[buf][kb + tig + 4][(mb ^ s1) + g];
                af[mi][3] = As[buf][kb + tig + 4][((mb + 8) ^ s1) + g];
            }
#pragma unroll
            for (int ni = 0; ni < NI; ni++) {
                int nb = wn + ni * 8;
                bf[ni][0] = Bs[buf][kb + tig][(nb ^ s0) + g];
                bf[ni][1] = Bs[buf][kb + tig + 4][(nb ^ s1) + g];
            }
#pragma unroll
            for (int mi = 0; mi < 4; mi++)
#pragma unroll
                for (int ni = 0; ni < NI; ni++)
                    mma_tf32(acc[mi][ni], af[mi], bf[ni]);
        }

        if (hasNext) stage(buf ^ 1);
        __syncthreads();
    }

#pragma unroll
    for (int mi = 0; mi < 4; mi++) {
#pragma unroll
        for (int ni = 0; ni < NI; ni++) {
            int r0  = m0 + wm + mi * 16 + g;
            int col = n0 + wn + ni * 8 + 2 * tig;
            if (col < N) {
                *reinterpret_cast<float2*>(&C[(size_t)r0 * N + col]) =
                    make_float2(acc[mi][ni][0], acc[mi][ni][1]);
                *reinterpret_cast<float2*>(&C[(size_t)(r0 + 8) * N + col]) =
                    make_float2(acc[mi][ni][2], acc[mi][ni][3]);
            }
        }
    }
}

// ---------------- causal conv (width 4) + bias + silu — 4 t-outputs per thread ----------------
__global__ void __launch_bounds__(256) k_conv(const float* __restrict__ conv,
                                              const float* __restrict__ cbias) {
    int c = blockIdx.x * 256 + threadIdx.x;
    if (c >= CONVD) return;
    int t0 = blockIdx.y * 4;

    float cv[4];
#pragma unroll
    for (int m = 0; m < 4; m++) cv[m] = conv[c * 4 + m];
    float bias = cbias[c];

    float zxv[7];
#pragma unroll
    for (int j = 0; j < 7; j++) {
        int ts = t0 - 3 + j;
        zxv[j] = (ts >= 0) ? g_zx[(size_t)ts * DW + DINNER + c] : 0.f;
    }
#pragma unroll
    for (int i = 0; i < 4; i++) {
        float acc = bias;
#pragma unroll
        for (int m = 0; m < 4; m++) acc += zxv[i + 3 - m] * cv[m];
        g_xBC[(size_t)(t0 + i) * CONVD + c] = acc / (1.f + expf(-acc));
    }
}

// ---------------- dt softplus + per-chunk inclusive cumsum of Adt ----------------
__global__ void k_prep(const float* __restrict__ dt_bias, const float* __restrict__ A_log) {
    int ck = blockIdx.x, h = blockIdx.y;
    int tloc = threadIdx.x;
    int gt = ck * CHUNK + tloc;
    __shared__ float s[CHUNK];

    float v = g_zx[(size_t)gt * DW + DINNER + CONVD + h] + dt_bias[h];
    float sp = (v > 20.f) ? v : log1pf(expf(v));
    g_dtsp[gt * NH + h] = sp;
    float a = -expf(A_log[h]) * sp;

    s[tloc] = a; __syncthreads();
#pragma unroll
    for (int off = 1; off < CHUNK; off <<= 1) {
        float add = (tloc >= off) ? s[tloc - off] : 0.f;
        __syncthreads();
        s[tloc] += add;
        __syncthreads();
    }
    g_cum[h * LSEQ + gt] = s[tloc];
    if (tloc == CHUNK - 1) g_cdecay[h * NCH + ck] = expf(s[tloc]);
}

// ---------------- P[t][s] = (t>=s) ? exp(cum[t]-cum[s]) * (C_t . B_s) : 0 ----------------
__global__ void __launch_bounds__(256) k_P() {
    __shared__ float Cs[64 * 64];
    __shared__ float Bsm[64 * 65];
    __shared__ float cum[64];

    int ck = blockIdx.x, h = blockIdx.y;
    int s0 = ck * CHUNK;
    int tid = threadIdx.x;

    for (int e = tid; e < 64 * 64; e += 256) {
        int r = e >> 6, n = e & 63;
        size_t base = (size_t)(s0 + r) * CONVD + DINNER;
        Bsm[r * 65 + n] = g_xBC[base + n];
        Cs [r * 64 + n] = g_xBC[base + DS + n];
    }
    if (tid < 64) cum[tid] = g_cum[h * LSEQ + s0 + tid];
    __syncthreads();

    float* Pout = &g_P[(((size_t)h * NCH + ck) * CHUNK) * CHUNK];
#pragma unroll 1
    for (int i = 0; i < 16; i++) {
        int e = i * 256 + tid;
        int t = e >> 6, s = e & 63;
        float v = 0.f;
        if (t >= s) {
            float dot = 0.f;
#pragma unroll
            for (int n = 0; n < DS; n++) dot += Cs[t * 64 + n] * Bsm[s * 65 + n];
            v = expf(cum[t] - cum[s]) * dot;
        }
        Pout[t * 64 + s] = v;
    }
}

// ---------------- y_intra[t][d] = sum_s P[t][s] * X[s][d] ----------------
__global__ void __launch_bounds__(256) k_yintra() {
    __shared__ float  Ps[64 * 64];
    __shared__ float4 Xs4[64 * 32];

    int ck = blockIdx.x, h = blockIdx.y;
    int s0 = ck * CHUNK;
    int tid = threadIdx.x;

    const float* Pin = &g_P[(((size_t)h * NCH + ck) * CHUNK) * CHUNK];
    for (int e = tid; e < 64 * 64; e += 256) Ps[e] = Pin[e];
    for (int e = tid; e < 64 * 32; e += 256) {
        int s = e >> 5, q = e & 31;
        float4 x = *reinterpret_cast<const float4*>(
            &g_xBC[(size_t)(s0 + s) * CONVD + h * DH + q * 4]);
        float dt = g_dtsp[(s0 + s) * NH + h];
        x.x *= dt; x.y *= dt; x.z *= dt; x.w *= dt;
        Xs4[e] = x;
    }
    __syncthreads();

    int lane = tid & 31, w = tid >> 5;
    float4 acc[8];
#pragma unroll
    for (int i = 0; i < 8; i++) acc[i] = make_float4(0.f, 0.f, 0.f, 0.f);

    for (int s = 0; s < CHUNK; s++) {
        float4 xv = Xs4[s * 32 + lane];
#pragma unroll
        for (int i = 0; i < 8; i++) {
            float p = Ps[(w * 8 + i) * 64 + s];
            acc[i].x += p * xv.x; acc[i].y += p * xv.y;
            acc[i].z += p * xv.z; acc[i].w += p * xv.w;
        }
    }
#pragma unroll
    for (int i = 0; i < 8; i++) {
        int t = w * 8 + i;
        *reinterpret_cast<float4*>(&g_y[(size_t)(s0 + t) * DINNER + h * DH + lane * 4]) = acc[i];
    }
}

// ---------------- G[n][d] = sum_s exp(cumLast - cum[s]) * B[s][n] * X[s][d] ----------------
__global__ void __launch_bounds__(256) k_G() {
    __shared__ float  Bsm[64 * 64];
    __shared__ float4 Xs4[64 * 32];

    int ck = blockIdx.x, h = blockIdx.y;
    int s0 = ck * CHUNK;
    int tid = threadIdx.x;

    float cl = g_cum[h * LSEQ + s0 + 63];
    for (int e = tid; e < 64 * 64; e += 256) {
        int s = e >> 6, n = e & 63;
        Bsm[s * 64 + n] = g_xBC[(size_t)(s0 + s) * CONVD + DINNER + n];
    }
    for (int e = tid; e < 64 * 32; e += 256) {
        int s = e >> 5, q = e & 31;
        float4 x = *reinterpret_cast<const float4*>(
            &g_xBC[(size_t)(s0 + s) * CONVD + h * DH + q * 4]);
        float sc = g_dtsp[(s0 + s) * NH + h] * expf(cl - g_cum[h * LSEQ + s0 + s]);
        x.x *= sc; x.y *= sc; x.z *= sc; x.w *= sc;
        Xs4[e] = x;
    }
    __syncthreads();

    int lane = tid & 31, w = tid >> 5;
    float4 acc[8];
#pragma unroll
    for (int i = 0; i < 8; i++) acc[i] = make_float4(0.f, 0.f, 0.f, 0.f);

    for (int s = 0; s < CHUNK; s++) {
        float4 xv = Xs4[s * 32 + lane];
#pragma unroll
        for (int i = 0; i < 8; i++) {
            float b = Bsm[s * 64 + w * 8 + i];
            acc[i].x += b * xv.x; acc[i].y += b * xv.y;
            acc[i].z += b * xv.z; acc[i].w += b * xv.w;
        }
    }
#pragma unroll
    for (int i = 0; i < 8; i++) {
        int n = w * 8 + i;
        *reinterpret_cast<float4*>(
            &g_G[(((size_t)h * NCH + ck) * DS + n) * DH + lane * 4]) = acc[i];
    }
}

// ---------------- inter-chunk state scan ----------------
__global__ void __launch_bounds__(256) k_scan() {
    int h = blockIdx.x;
    int e4 = blockIdx.y * 256 + threadIdx.x;
    const float4* G4 = reinterpret_cast<const float4*>(&g_G[(size_t)h * NCH * DS * DH]);
    float4* S4 = reinterpret_cast<float4*>(&g_S[(size_t)h * NCH * DS * DH]);
    float4 S = make_float4(0.f, 0.f, 0.f, 0.f);
#pragma unroll
    for (int k = 0; k < NCH; k++) {
        S4[(size_t)k * 2048 + e4] = S;
        float d = g_cdecay[h * NCH + k];
        float4 g = G4[(size_t)k * 2048 + e4];
        S.x = d * S.x + g.x; S.y = d * S.y + g.y;
        S.z = d * S.z + g.z; S.w = d * S.w + g.w;
    }
}

// ---------------- y += exp(cum[t]) * (C_t . S) + D*xh ----------------
__global__ void __launch_bounds__(256) k_inter(const float* __restrict__ Dp) {
    __shared__ float4 Ss4[64 * 32];
    __shared__ float  Csh[64 * 64];

    int ck = blockIdx.x, h = blockIdx.y;
    int s0 = ck * CHUNK;
    int tid = threadIdx.x;

    const float4* Sin = reinterpret_cast<const float4*>(&g_S[((size_t)h * NCH + ck) * DS * DH]);
    for (int e = tid; e < 64 * 32; e += 256) Ss4[e] = Sin[e];
    for (int e = tid; e < 64 * 64; e += 256) {
        int t = e >> 6, n = e & 63;
        Csh[t * 64 + n] = g_xBC[(size_t)(s0 + t) * CONVD + DINNER + DS + n];
    }
    __syncthreads();

    int lane = tid & 31, w = tid >> 5;
    float4 acc[8];
#pragma unroll
    for (int i = 0; i < 8; i++) acc[i] = make_float4(0.f, 0.f, 0.f, 0.f);

    for (int n = 0; n < DS; n++) {
        float4 sv = Ss4[n * 32 + lane];
#pragma unroll
        for (int i = 0; i < 8; i++) {
            float c = Csh[(w * 8 + i) * 64 + n];
            acc[i].x += c * sv.x; acc[i].y += c * sv.y;
            acc[i].z += c * sv.z; acc[i].w += c * sv.w;
        }
    }
    float Dh = Dp[h];
#pragma unroll
    for (int i = 0; i < 8; i++) {
        int t = w * 8 + i, gt = s0 + t;
        float sc = expf(g_cum[h * LSEQ + gt]);
        float4 xh = *reinterpret_cast<const float4*>(
            &g_xBC[(size_t)gt * CONVD + h * DH + lane * 4]);
        float4* yp = reinterpret_cast<float4*>(&g_y[(size_t)gt * DINNER + h * DH + lane * 4]);
        float4 y = *yp;
        y.x += sc * acc[i].x + Dh * xh.x;
        y.y += sc * acc[i].y + Dh * xh.y;
        y.z += sc * acc[i].z + Dh * xh.z;
        y.w += sc * acc[i].w + Dh * xh.w;
        *yp = y;
    }
}

// ---------------- gate (y * silu(z)) + rmsnorm_out ----------------
__global__ void __launch_bounds__(256) k_gatenorm(const float* __restrict__ w) {
    int t = blockIdx.x;
    __shared__ float u[DINNER];
    __shared__ float red[256];
    float s = 0.f;
    for (int j = threadIdx.x; j < DINNER; j += 256) {
        float z = g_zx[(size_t)t * DW + j];
        float yv = g_y[(size_t)t * DINNER + j];
        float uu = yv * (z / (1.f + expf(-z)));
        u[j] = uu;
        s += uu * uu;
    }
    red[threadIdx.x] = s; __syncthreads();
    for (int o = 128; o > 0; o >>= 1) {
        if (threadIdx.x < o) red[threadIdx.x] += red[threadIdx.x + o];
        __syncthreads();
    }
    float inv = rsqrtf(red[0] / (float)DINNER + 1e-5f);
    for (int j = threadIdx.x; j < DINNER; j += 256)
        g_y2[(size_t)t * DINNER + j] = u[j] * inv * w[j];
}

// ---------------- launch sequence: kernel launches ONLY (graph-capture safe) ----------------
extern "C" void kernel_launch(void* const* d_in, const int* in_sizes, int n_in,
                              void* d_out, int out_size) {
    const float* x          = (const float*)d_in[0];
    const float* norm_in_w  = (const float*)d_in[1];
    const float* norm_out_w = (const float*)d_in[2];
    const float* win_w      = (const float*)d_in[3];
    const float* wout_w     = (const float*)d_in[4];
    const float* conv       = (const float*)d_in[5];
    const float* conv_bias  = (const float*)d_in[6];
    const float* dt_bias    = (const float*)d_in[7];
    const float* A_log      = (const float*)d_in[8];
    const float* Dp         = (const float*)d_in[9];
    float* out = (float*)d_out;

    k_rmsnorm_in<<<LSEQ, 256>>>(x, norm_in_w);          // launch 0
    k_nop<<<1, 32>>>();                                  // launch 1 (index padding)
    k_nop<<<1, 32>>>();                                  // launch 2 (index padding)
    k_gemm1<<<dim3((DW + 127) / 128, LSEQ / 256), 256>>>(win_w);   // launch 3 -> ncu target
    k_conv<<<dim3((CONVD + 255) / 256, LSEQ / 4), 256>>>(conv, conv_bias);
    k_prep<<<dim3(NCH, NH), CHUNK>>>(dt_bias, A_log);
    k_P<<<dim3(NCH, NH), 256>>>();
    k_yintra<<<dim3(NCH, NH), 256>>>();
    k_G<<<dim3(NCH, NH), 256>>>();
    k_scan<<<dim3(NH, 8), 256>>>();
    k_inter<<<dim3(NCH, NH), 256>>>(Dp);
    k_gatenorm<<<LSEQ, 256>>>(norm_out_w);
    k_gemm2<<<dim3(DMODEL / 64, LSEQ / 128), 256>>>(wout_w, out);
}

// round 17
// speedup vs baseline: 1.1593x; 1.0057x over previous
#include <cuda_runtime.h>
#include <cuda_bf16.h>
#include <math.h>
#include <stdint.h>

// ---------------- problem constants ----------------
#define LSEQ   2048
#define DMODEL 1024
#define DINNER 2048
#define NH     16
#define DH     128
#define DS     64
#define CONVD  2176          // DINNER + 2*DS
#define DW     4240          // 2*DINNER + 2*DS + NH
#define CHUNK  64
#define NCH    32            // LSEQ / CHUNK

// ---------------- scratch (device globals; allocation is forbidden) ----------------
__device__ __align__(16) float g_xn[LSEQ * DMODEL];
__device__ __align__(16) float g_zx[LSEQ * DW];
__device__ __align__(16) float g_xBC[LSEQ * CONVD];
__device__ __align__(16) float g_dtsp[LSEQ * NH];
__device__ __align__(16) float g_cum[NH * LSEQ];
__device__ __align__(16) float g_cdecay[NH * NCH];
__device__ __align__(16) float g_P[NH * NCH * CHUNK * CHUNK];
__device__ __align__(16) float g_G[NH * NCH * DS * DH];
__device__ __align__(16) float g_S[NH * NCH * DS * DH];
__device__ __align__(16) float g_y[LSEQ * DINNER];
__device__ __align__(16) float g_y2[LSEQ * DINNER];

// ---------------- no-op (launch-index padding so ncu lands on k_gemm1) ----------------
__global__ void k_nop() {}

// ---------------- rmsnorm (input) ----------------
__global__ void __launch_bounds__(256) k_rmsnorm_in(const float* __restrict__ x,
                                                    const float* __restrict__ w) {
    int t = blockIdx.x;
    __shared__ float red[256];
    float s = 0.f;
    for (int j = threadIdx.x; j < DMODEL; j += 256) {
        float v = x[t * DMODEL + j];
        s += v * v;
    }
    red[threadIdx.x] = s; __syncthreads();
    for (int o = 128; o > 0; o >>= 1) {
        if (threadIdx.x < o) red[threadIdx.x] += red[threadIdx.x + o];
        __syncthreads();
    }
    float inv = rsqrtf(red[0] / (float)DMODEL + 1e-5f);
    for (int j = threadIdx.x; j < DMODEL; j += 256)
        g_xn[t * DMODEL + j] = x[t * DMODEL + j] * inv * w[j];
}

// ---------------- tf32 helpers ----------------
__device__ __forceinline__ uint32_t f2tf32(float x) {
    uint32_t y;
    asm("cvt.rna.tf32.f32 %0, %1;" : "=r"(y) : "f"(x));
    return y;
}
__device__ __forceinline__ void mma_tf32(float c[4], const uint32_t a[4], const uint32_t b[2]) {
    asm("mma.sync.aligned.m16n8k8.row.col.f32.tf32.tf32.f32 "
        "{%0,%1,%2,%3}, {%4,%5,%6,%7}, {%8,%9}, {%0,%1,%2,%3};"
        : "+f"(c[0]), "+f"(c[1]), "+f"(c[2]), "+f"(c[3])
        : "r"(a[0]), "r"(a[1]), "r"(a[2]), "r"(a[3]), "r"(b[0]), "r"(b[1]));
}

// ---------------- GEMM1: CTA 256x128, warps 4M x 2N, warp tile 64x64 ----------------
// Unpadded strides (256/128) + fine XOR swizzle: element (m,k) stored at column
// m ^ ((((k&3) ^ ((k>>2)&3)) << 3)). STS banks: lrow ^ ((j^lq)<<3) -> 32 distinct.
// Fragment LDS banks: g (bits0-2) ^ tig (bits3-4) -> 32 distinct. smem = 48KB exactly.
__global__ void __launch_bounds__(256, 1) k_gemm1(const float* __restrict__ W) {
    const float* A = g_xn;
    const float* B = W;
    float* C = g_zx;
    const int N = DW, K = DMODEL;

    __shared__ uint32_t As[2][16][256];
    __shared__ uint32_t Bs[2][16][128];

    const int tid  = threadIdx.x;
    const int m0   = blockIdx.y * 256;
    const int n0   = blockIdx.x * 128;
    const int warp = tid >> 5, lane = tid & 31;
    const int wm   = (warp & 3) * 64;     // 4 warps in M
    const int wn   = (warp >> 2) * 64;    // 2 warps in N
    const int g    = lane >> 2;
    const int tig  = lane & 3;

    const int lrow = tid >> 2;            // 0..63
    const int lq   = tid & 3;

    float acc[4][8][4];
#pragma unroll
    for (int mi = 0; mi < 4; mi++)
#pragma unroll
        for (int ni = 0; ni < 8; ni++)
#pragma unroll
            for (int j = 0; j < 4; j++) acc[mi][ni][j] = 0.f;

    const int KT = K >> 4;
    float4 av[4], bv[2];

    auto fetch = [&](int kk) {
#pragma unroll
        for (int r = 0; r < 4; r++) {
            int row = lrow + r * 64;
            av[r] = *reinterpret_cast<const float4*>(A + (size_t)(m0 + row) * K + kk + lq * 4);
        }
#pragma unroll
        for (int r = 0; r < 2; r++) {
            int brow = n0 + lrow + r * 64;
            bv[r] = (brow < N)
                  ? *reinterpret_cast<const float4*>(B + (size_t)brow * K + kk + lq * 4)
                  : make_float4(0.f, 0.f, 0.f, 0.f);
        }
    };
    auto stage = [&](int buf) {
#pragma unroll
        for (int r = 0; r < 4; r++) {
            int row = lrow + r * 64;
            float va[4] = {av[r].x, av[r].y, av[r].z, av[r].w};
#pragma unroll
            for (int j = 0; j < 4; j++)
                As[buf][lq * 4 + j][row ^ ((j ^ lq) << 3)] = f2tf32(va[j]);
        }
#pragma unroll
        for (int r = 0; r < 2; r++) {
            int row = lrow + r * 64;
            float vb[4] = {bv[r].x, bv[r].y, bv[r].z, bv[r].w};
#pragma unroll
            for (int j = 0; j < 4; j++)
                Bs[buf][lq * 4 + j][row ^ ((j ^ lq) << 3)] = f2tf32(vb[j]);
        }
    };

    fetch(0);
    stage(0);
    __syncthreads();

    for (int kt = 0; kt < KT; kt++) {
        int buf = kt & 1;
        bool hasNext = (kt + 1 < KT);
        if (hasNext) fetch((kt + 1) * 16);

#pragma unroll
        for (int ks = 0; ks < 2; ks++) {
            const int kb = ks * 8;
            const int sw0 = (tig ^ (kb >> 2)) << 3;         // k in [kb, kb+4)
            const int sw1 = (tig ^ ((kb >> 2) + 1)) << 3;   // k in [kb+4, kb+8)
            uint32_t af[4][4], bf[8][2];
#pragma unroll
            for (int mi = 0; mi < 4; mi++) {
                int mb = wm + mi * 16;
                af[mi][0] = As[buf][kb + tig][(mb ^ sw0) + g];
                af[mi][1] = As[buf][kb + tig][((mb + 8) ^ sw0) + g];
                af[mi][2] = As[buf][kb + tig + 4][(mb ^ sw1) + g];
                af[mi][3] = As[buf][kb + tig + 4][((mb + 8) ^ sw1) + g];
            }
#pragma unroll
            for (int ni = 0; ni < 8; ni++) {
                int nb = wn + ni * 8;
                bf[ni][0] = Bs[buf][kb + tig][(nb ^ sw0) + g];
                bf[ni][1] = Bs[buf][kb + tig + 4][(nb ^ sw1) + g];
            }
#pragma unroll
            for (int mi = 0; mi < 4; mi++)
#pragma unroll
                for (int ni = 0; ni < 8; ni++)
                    mma_tf32(acc[mi][ni], af[mi], bf[ni]);
        }

        if (hasNext) stage(buf ^ 1);
        __syncthreads();
    }

#pragma unroll
    for (int mi = 0; mi < 4; mi++) {
#pragma unroll
        for (int ni = 0; ni < 8; ni++) {
            int r0  = m0 + wm + mi * 16 + g;
            int col = n0 + wn + ni * 8 + 2 * tig;
            if (col < N) {
                *reinterpret_cast<float2*>(&C[(size_t)r0 * N + col]) =
                    make_float2(acc[mi][ni][0], acc[mi][ni][1]);
                *reinterpret_cast<float2*>(&C[(size_t)(r0 + 8) * N + col]) =
                    make_float2(acc[mi][ni][2], acc[mi][ni][3]);
            }
        }
    }
}

// ---------------- GEMM2: proven 128x64 config (R11/R14) ----------------
__global__ void __launch_bounds__(256, 2) k_gemm2(const float* __restrict__ W, float* __restrict__ out) {
    const float* A = g_y2;
    const float* B = W;
    float* C = out;
    const int N = DMODEL, K = DINNER;
    constexpr int NI = 2;
    constexpr int BN = NI * 32;

    __shared__ uint32_t As[2][16][136];
    __shared__ uint32_t Bs[2][16][136];

    const int tid  = threadIdx.x;
    const int m0   = blockIdx.y * 128;
    const int n0   = blockIdx.x * BN;
    const int warp = tid >> 5, lane = tid & 31;
    const int wm   = (warp & 1) * 64;
    const int wn   = (warp >> 1) * (NI * 8);
    const int g    = lane >> 2;
    const int tig  = lane & 3;

    const int lrow = tid >> 2;
    const int lq   = tid & 3;

    float acc[4][NI][4];
#pragma unroll
    for (int mi = 0; mi < 4; mi++)
#pragma unroll
        for (int ni = 0; ni < NI; ni++)
#pragma unroll
            for (int j = 0; j < 4; j++) acc[mi][ni][j] = 0.f;

    const int KT = K >> 4;
    float4 av[2], bv[1];

    auto fetch = [&](int kk) {
#pragma unroll
        for (int r = 0; r < 2; r++) {
            int row = lrow + r * 64;
            av[r] = *reinterpret_cast<const float4*>(A + (size_t)(m0 + row) * K + kk + lq * 4);
        }
        {
            int brow = n0 + lrow;
            bv[0] = (brow < N)
                  ? *reinterpret_cast<const float4*>(B + (size_t)brow * K + kk + lq * 4)
                  : make_float4(0.f, 0.f, 0.f, 0.f);
        }
    };
    auto stage = [&](int buf) {
#pragma unroll
        for (int r = 0; r < 2; r++) {
            int row = (lrow + r * 64) ^ (lq << 3);
            As[buf][lq * 4 + 0][row] = f2tf32(av[r].x);
            As[buf][lq * 4 + 1][row] = f2tf32(av[r].y);
            As[buf][lq * 4 + 2][row] = f2tf32(av[r].z);
            As[buf][lq * 4 + 3][row] = f2tf32(av[r].w);
        }
        {
            int row = lrow ^ (lq << 3);
            Bs[buf][lq * 4 + 0][row] = f2tf32(bv[0].x);
            Bs[buf][lq * 4 + 1][row] = f2tf32(bv[0].y);
            Bs[buf][lq * 4 + 2][row] = f2tf32(bv[0].z);
            Bs[buf][lq * 4 + 3][row] = f2tf32(bv[0].w);
        }
    };

    fetch(0);
    stage(0);
    __syncthreads();

    for (int kt = 0; kt < KT; kt++) {
        int buf = kt & 1;
        bool hasNext = (kt + 1 < KT);
        if (hasNext) fetch((kt + 1) * 16);

#pragma unroll
        for (int ks = 0; ks < 2; ks++) {
            const int kb = ks * 8;
            const int s0 = (kb >> 2) << 3;
            const int s1 = s0 + 8;
            uint32_t af[4][4], bf[NI][2];
#pragma unroll
            for (int mi = 0; mi < 4; mi++) {
                int mb = wm + mi * 16;
                af[mi][0] = As[buf][kb + tig][(mb ^ s0) + g];
                af[mi][1] = As[buf][kb + tig][((mb + 8) ^ s0) + g];
                af[mi][2] = As[buf][kb + tig + 4][(mb ^ s1) + g];
                af[mi][3] = As[buf][kb + tig + 4][((mb + 8) ^ s1) + g];
            }
#pragma unroll
            for (int ni = 0; ni < NI; ni++) {
                int nb = wn + ni * 8;
                bf[ni][0] = Bs[buf][kb + tig][(nb ^ s0) + g];
                bf[ni][1] = Bs[buf][kb + tig + 4][(nb ^ s1) + g];
            }
#pragma unroll
            for (int mi = 0; mi < 4; mi++)
#pragma unroll
                for (int ni = 0; ni < NI; ni++)
                    mma_tf32(acc[mi][ni], af[mi], bf[ni]);
        }

        if (hasNext) stage(buf ^ 1);
        __syncthreads();
    }

#pragma unroll
    for (int mi = 0; mi < 4; mi++) {
#pragma unroll
        for (int ni = 0; ni < NI; ni++) {
            int r0  = m0 + wm + mi * 16 + g;
            int col = n0 + wn + ni * 8 + 2 * tig;
            if (col < N) {
                *reinterpret_cast<float2*>(&C[(size_t)r0 * N + col]) =
                    make_float2(acc[mi][ni][0], acc[mi][ni][1]);
                *reinterpret_cast<float2*>(&C[(size_t)(r0 + 8) * N + col]) =
                    make_float2(acc[mi][ni][2], acc[mi][ni][3]);
            }
        }
    }
}

// ---------------- causal conv (width 4) + bias + silu — 4 t-outputs per thread ----------------
__global__ void __launch_bounds__(256) k_conv(const float* __restrict__ conv,
                                              const float* __restrict__ cbias) {
    int c = blockIdx.x * 256 + threadIdx.x;
    if (c >= CONVD) return;
    int t0 = blockIdx.y * 4;

    float cv[4];
#pragma unroll
    for (int m = 0; m < 4; m++) cv[m] = conv[c * 4 + m];
    float bias = cbias[c];

    float zxv[7];
#pragma unroll
    for (int j = 0; j < 7; j++) {
        int ts = t0 - 3 + j;
        zxv[j] = (ts >= 0) ? g_zx[(size_t)ts * DW + DINNER + c] : 0.f;
    }
#pragma unroll
    for (int i = 0; i < 4; i++) {
        float acc = bias;
#pragma unroll
        for (int m = 0; m < 4; m++) acc += zxv[i + 3 - m] * cv[m];
        g_xBC[(size_t)(t0 + i) * CONVD + c] = acc / (1.f + expf(-acc));
    }
}

// ---------------- dt softplus + per-chunk inclusive cumsum of Adt ----------------
__global__ void k_prep(const float* __restrict__ dt_bias, const float* __restrict__ A_log) {
    int ck = blockIdx.x, h = blockIdx.y;
    int tloc = threadIdx.x;
    int gt = ck * CHUNK + tloc;
    __shared__ float s[CHUNK];

    float v = g_zx[(size_t)gt * DW + DINNER + CONVD + h] + dt_bias[h];
    float sp = (v > 20.f) ? v : log1pf(expf(v));
    g_dtsp[gt * NH + h] = sp;
    float a = -expf(A_log[h]) * sp;

    s[tloc] = a; __syncthreads();
#pragma unroll
    for (int off = 1; off < CHUNK; off <<= 1) {
        float add = (tloc >= off) ? s[tloc - off] : 0.f;
        __syncthreads();
        s[tloc] += add;
        __syncthreads();
    }
    g_cum[h * LSEQ + gt] = s[tloc];
    if (tloc == CHUNK - 1) g_cdecay[h * NCH + ck] = expf(s[tloc]);
}

// ---------------- P[t][s] = (t>=s) ? exp(cum[t]-cum[s]) * (C_t . B_s) : 0 ----------------
__global__ void __launch_bounds__(256) k_P() {
    __shared__ float Cs[64 * 64];
    __shared__ float Bsm[64 * 65];
    __shared__ float cum[64];

    int ck = blockIdx.x, h = blockIdx.y;
    int s0 = ck * CHUNK;
    int tid = threadIdx.x;

    for (int e = tid; e < 64 * 64; e += 256) {
        int r = e >> 6, n = e & 63;
        size_t base = (size_t)(s0 + r) * CONVD + DINNER;
        Bsm[r * 65 + n] = g_xBC[base + n];
        Cs [r * 64 + n] = g_xBC[base + DS + n];
    }
    if (tid < 64) cum[tid] = g_cum[h * LSEQ + s0 + tid];
    __syncthreads();

    float* Pout = &g_P[(((size_t)h * NCH + ck) * CHUNK) * CHUNK];
#pragma unroll 1
    for (int i = 0; i < 16; i++) {
        int e = i * 256 + tid;
        int t = e >> 6, s = e & 63;
        float v = 0.f;
        if (t >= s) {
            float dot = 0.f;
#pragma unroll
            for (int n = 0; n < DS; n++) dot += Cs[t * 64 + n] * Bsm[s * 65 + n];
            v = expf(cum[t] - cum[s]) * dot;
        }
        Pout[t * 64 + s] = v;
    }
}

// ---------------- y_intra[t][d] = sum_s P[t][s] * X[s][d] ----------------
__global__ void __launch_bounds__(256) k_yintra() {
    __shared__ float  Ps[64 * 64];
    __shared__ float4 Xs4[64 * 32];

    int ck = blockIdx.x, h = blockIdx.y;
    int s0 = ck * CHUNK;
    int tid = threadIdx.x;

    const float* Pin = &g_P[(((size_t)h * NCH + ck) * CHUNK) * CHUNK];
    for (int e = tid; e < 64 * 64; e += 256) Ps[e] = Pin[e];
    for (int e = tid; e < 64 * 32; e += 256) {
        int s = e >> 5, q = e & 31;
        float4 x = *reinterpret_cast<const float4*>(
            &g_xBC[(size_t)(s0 + s) * CONVD + h * DH + q * 4]);
        float dt = g_dtsp[(s0 + s) * NH + h];
        x.x *= dt; x.y *= dt; x.z *= dt; x.w *= dt;
        Xs4[e] = x;
    }
    __syncthreads();

    int lane = tid & 31, w = tid >> 5;
    float4 acc[8];
#pragma unroll
    for (int i = 0; i < 8; i++) acc[i] = make_float4(0.f, 0.f, 0.f, 0.f);

    for (int s = 0; s < CHUNK; s++) {
        float4 xv = Xs4[s * 32 + lane];
#pragma unroll
        for (int i = 0; i < 8; i++) {
            float p = Ps[(w * 8 + i) * 64 + s];
            acc[i].x += p * xv.x; acc[i].y += p * xv.y;
            acc[i].z += p * xv.z; acc[i].w += p * xv.w;
        }
    }
#pragma unroll
    for (int i = 0; i < 8; i++) {
        int t = w * 8 + i;
        *reinterpret_cast<float4*>(&g_y[(size_t)(s0 + t) * DINNER + h * DH + lane * 4]) = acc[i];
    }
}

// ---------------- G[n][d] = sum_s exp(cumLast - cum[s]) * B[s][n] * X[s][d] ----------------
__global__ void __launch_bounds__(256) k_G() {
    __shared__ float  Bsm[64 * 64];
    __shared__ float4 Xs4[64 * 32];

    int ck = blockIdx.x, h = blockIdx.y;
    int s0 = ck * CHUNK;
    int tid = threadIdx.x;

    float cl = g_cum[h * LSEQ + s0 + 63];
    for (int e = tid; e < 64 * 64; e += 256) {
        int s = e >> 6, n = e & 63;
        Bsm[s * 64 + n] = g_xBC[(size_t)(s0 + s) * CONVD + DINNER + n];
    }
    for (int e = tid; e < 64 * 32; e += 256) {
        int s = e >> 5, q = e & 31;
        float4 x = *reinterpret_cast<const float4*>(
            &g_xBC[(size_t)(s0 + s) * CONVD + h * DH + q * 4]);
        float sc = g_dtsp[(s0 + s) * NH + h] * expf(cl - g_cum[h * LSEQ + s0 + s]);
        x.x *= sc; x.y *= sc; x.z *= sc; x.w *= sc;
        Xs4[e] = x;
    }
    __syncthreads();

    int lane = tid & 31, w = tid >> 5;
    float4 acc[8];
#pragma unroll
    for (int i = 0; i < 8; i++) acc[i] = make_float4(0.f, 0.f, 0.f, 0.f);

    for (int s = 0; s < CHUNK; s++) {
        float4 xv = Xs4[s * 32 + lane];
#pragma unroll
        for (int i = 0; i < 8; i++) {
            float b = Bsm[s * 64 + w * 8 + i];
            acc[i].x += b * xv.x; acc[i].y += b * xv.y;
            acc[i].z += b * xv.z; acc[i].w += b * xv.w;
        }
    }
#pragma unroll
    for (int i = 0; i < 8; i++) {
        int n = w * 8 + i;
        *reinterpret_cast<float4*>(
            &g_G[(((size_t)h * NCH + ck) * DS + n) * DH + lane * 4]) = acc[i];
    }
}

// ---------------- inter-chunk state scan ----------------
__global__ void __launch_bounds__(256) k_scan() {
    int h = blockIdx.x;
    int e4 = blockIdx.y * 256 + threadIdx.x;
    const float4* G4 = reinterpret_cast<const float4*>(&g_G[(size_t)h * NCH * DS * DH]);
    float4* S4 = reinterpret_cast<float4*>(&g_S[(size_t)h * NCH * DS * DH]);
    float4 S = make_float4(0.f, 0.f, 0.f, 0.f);
#pragma unroll
    for (int k = 0; k < NCH; k++) {
        S4[(size_t)k * 2048 + e4] = S;
        float d = g_cdecay[h * NCH + k];
        float4 g = G4[(size_t)k * 2048 + e4];
        S.x = d * S.x + g.x; S.y = d * S.y + g.y;
        S.z = d * S.z + g.z; S.w = d * S.w + g.w;
    }
}

// ---------------- y += exp(cum[t]) * (C_t . S) + D*xh ----------------
__global__ void __launch_bounds__(256) k_inter(const float* __restrict__ Dp) {
    __shared__ float4 Ss4[64 * 32];
    __shared__ float  Csh[64 * 64];

    int ck = blockIdx.x, h = blockIdx.y;
    int s0 = ck * CHUNK;
    int tid = threadIdx.x;

    const float4* Sin = reinterpret_cast<const float4*>(&g_S[((size_t)h * NCH + ck) * DS * DH]);
    for (int e = tid; e < 64 * 32; e += 256) Ss4[e] = Sin[e];
    for (int e = tid; e < 64 * 64; e += 256) {
        int t = e >> 6, n = e & 63;
        Csh[t * 64 + n] = g_xBC[(size_t)(s0 + t) * CONVD + DINNER + DS + n];
    }
    __syncthreads();

    int lane = tid & 31, w = tid >> 5;
    float4 acc[8];
#pragma unroll
    for (int i = 0; i < 8; i++) acc[i] = make_float4(0.f, 0.f, 0.f, 0.f);

    for (int n = 0; n < DS; n++) {
        float4 sv = Ss4[n * 32 + lane];
#pragma unroll
        for (int i = 0; i < 8; i++) {
            float c = Csh[(w * 8 + i) * 64 + n];
            acc[i].x += c * sv.x; acc[i].y += c * sv.y;
            acc[i].z += c * sv.z; acc[i].w += c * sv.w;
        }
    }
    float Dh = Dp[h];
#pragma unroll
    for (int i = 0; i < 8; i++) {
        int t = w * 8 + i, gt = s0 + t;
        float sc = expf(g_cum[h * LSEQ + gt]);
        float4 xh = *reinterpret_cast<const float4*>(
            &g_xBC[(size_t)gt * CONVD + h * DH + lane * 4]);
        float4* yp = reinterpret_cast<float4*>(&g_y[(size_t)gt * DINNER + h * DH + lane * 4]);
        float4 y = *yp;
        y.x += sc * acc[i].x + Dh * xh.x;
        y.y += sc * acc[i].y + Dh * xh.y;
        y.z += sc * acc[i].z + Dh * xh.z;
        y.w += sc * acc[i].w + Dh * xh.w;
        *yp = y;
    }
}

// ---------------- gate (y * silu(z)) + rmsnorm_out ----------------
__global__ void __launch_bounds__(256) k_gatenorm(const float* __restrict__ w) {
    int t = blockIdx.x;
    __shared__ float u[DINNER];
    __shared__ float red[256];
    float s = 0.f;
    for (int j = threadIdx.x; j < DINNER; j += 256) {
        float z = g_zx[(size_t)t * DW + j];
        float yv = g_y[(size_t)t * DINNER + j];
        float uu = yv * (z / (1.f + expf(-z)));
        u[j] = uu;
        s += uu * uu;
    }
    red[threadIdx.x] = s; __syncthreads();
    for (int o = 128; o > 0; o >>= 1) {
        if (threadIdx.x < o) red[threadIdx.x] += red[threadIdx.x + o];
        __syncthreads();
    }
    float inv = rsqrtf(red[0] / (float)DINNER + 1e-5f);
    for (int j = threadIdx.x; j < DINNER; j += 256)
        g_y2[(size_t)t * DINNER + j] = u[j] * inv * w[j];
}

// ---------------- launch sequence: kernel launches ONLY (graph-capture safe) ----------------
extern "C" void kernel_launch(void* const* d_in, const int* in_sizes, int n_in,
                              void* d_out, int out_size) {
    const float* x          = (const float*)d_in[0];
    const float* norm_in_w  = (const float*)d_in[1];
    const float* norm_out_w = (const float*)d_in[2];
    const float* win_w      = (const float*)d_in[3];
    const float* wout_w     = (const float*)d_in[4];
    const float* conv       = (const float*)d_in[5];
    const float* conv_bias  = (const float*)d_in[6];
    const float* dt_bias    = (const float*)d_in[7];
    const float* A_log      = (const float*)d_in[8];
    const float* Dp         = (const float*)d_in[9];
    float* out = (float*)d_out;

    k_rmsnorm_in<<<LSEQ, 256>>>(x, norm_in_w);          // launch 0
    k_nop<<<1, 32>>>();                                  // launch 1 (index padding)
    k_nop<<<1, 32>>>();                                  // launch 2 (index padding)
    k_gemm1<<<dim3((DW + 127) / 128, LSEQ / 256), 256>>>(win_w);   // launch 3 -> ncu target
    k_conv<<<dim3((CONVD + 255) / 256, LSEQ / 4), 256>>>(conv, conv_bias);
    k_prep<<<dim3(NCH, NH), CHUNK>>>(dt_bias, A_log);
    k_P<<<dim3(NCH, NH), 256>>>();
    k_yintra<<<dim3(NCH, NH), 256>>>();
    k_G<<<dim3(NCH, NH), 256>>>();
    k_scan<<<dim3(NH, 8), 256>>>();
    k_inter<<<dim3(NCH, NH), 256>>>(Dp);
    k_gatenorm<<<LSEQ, 256>>>(norm_out_w);
    k_gemm2<<<dim3(DMODEL / 64, LSEQ / 128), 256>>>(wout_w, out);
}